// round 13
// baseline (speedup 1.0000x reference)
#include <cuda_runtime.h>
#include <cuda_fp16.h>
#include <cstdint>

#define NN 100000
#define NE 1600000
#define H  64
#define SCAN_B 1024
#define NBLK ((NN + SCAN_B - 1) / SCAN_B)   // 98

// ---------------- scratch (device globals; no allocation) ----------------
__device__ __half g_ew[1600000ull * 64];  // edge weights fp16, CSR-slot order [E,64]
__device__ int    g_cnt[NN];
__device__ int    g_off[NN + 1];
__device__ int    g_cur[NN];
__device__ int    g_src[NE];              // CSR-slot -> source node
__device__ int    g_pos[NE];              // edge e -> CSR slot
__device__ int    g_bsum[NBLK];
__device__ int    g_boff[NBLK];
__device__ float  g_xlin[NN * H];
__device__ float  g_dinv[NN * H];
__device__ __half g_y[NN * H];            // fp16 gather operand
__device__ float  g_hagg[NN * H];
__device__ float  g_h[NN * H];

// ---------------- CSR build ----------------
__global__ void k_zero() {
    int i = blockIdx.x * blockDim.x + threadIdx.x;
    if (i < NN) g_cnt[i] = 0;
}

__global__ void k_count(const int* __restrict__ ei) {
    int e = blockIdx.x * blockDim.x + threadIdx.x;
    if (e < NE) {
        int c = ei[NE + e];
        if ((unsigned)c < (unsigned)NN) atomicAdd(&g_cnt[c], 1);
    }
}

// ---- hierarchical scan ----
__global__ void __launch_bounds__(1024) k_scan_sum() {
    __shared__ int s[1024];
    int t = threadIdx.x, b = blockIdx.x;
    int i = b * SCAN_B + t;
    s[t] = (i < NN) ? g_cnt[i] : 0;
    __syncthreads();
#pragma unroll
    for (int d = 512; d > 0; d >>= 1) {
        if (t < d) s[t] += s[t + d];
        __syncthreads();
    }
    if (t == 0) g_bsum[b] = s[0];
}

__global__ void __launch_bounds__(128) k_scan_top() {
    __shared__ int s[128];
    int t = threadIdx.x;
    int v = (t < NBLK) ? g_bsum[t] : 0;
    s[t] = v;
    __syncthreads();
#pragma unroll
    for (int d = 1; d < 128; d <<= 1) {
        int u = (t >= d) ? s[t - d] : 0;
        __syncthreads();
        s[t] += u;
        __syncthreads();
    }
    if (t < NBLK) g_boff[t] = s[t] - v;
    if (t == NBLK - 1) g_off[NN] = s[t];
}

__global__ void __launch_bounds__(1024) k_scan_apply() {
    __shared__ int s[1024];
    int t = threadIdx.x, b = blockIdx.x;
    int i = b * SCAN_B + t;
    int v = (i < NN) ? g_cnt[i] : 0;
    s[t] = v;
    __syncthreads();
#pragma unroll
    for (int d = 1; d < 1024; d <<= 1) {
        int u = (t >= d) ? s[t - d] : 0;
        __syncthreads();
        s[t] += u;
        __syncthreads();
    }
    if (i < NN) {
        int off = g_boff[b] + s[t] - v;
        g_off[i] = off;
        g_cur[i] = off;
    }
}

__global__ void k_fill(const int* __restrict__ ei) {
    int e = blockIdx.x * blockDim.x + threadIdx.x;
    if (e < NE) {
        int c = ei[NE + e];
        int r = ei[e];
        if ((unsigned)c >= (unsigned)NN || (unsigned)r >= (unsigned)NN) return;
        int p = atomicAdd(&g_cur[c], 1);
        g_src[p] = r;
        g_pos[e] = p;
    }
}

// ---------------- mma.m16n8k16 f32 += f16 x f16 ----------------
__device__ __forceinline__ void mma16816(float c[4], const uint32_t a[4],
                                         uint32_t b0, uint32_t b1) {
    asm volatile(
        "mma.sync.aligned.m16n8k16.row.col.f32.f16.f16.f32 "
        "{%0,%1,%2,%3}, {%4,%5,%6,%7}, {%8,%9}, {%0,%1,%2,%3};"
        : "+f"(c[0]), "+f"(c[1]), "+f"(c[2]), "+f"(c[3])
        : "r"(a[0]), "r"(a[1]), "r"(a[2]), "r"(a[3]), "r"(b0), "r"(b1));
}

// ---------------- edge MLP, BOTH stages on tensor cores ----------------
__global__ void __launch_bounds__(256) k_ew(const float* __restrict__ ea,
                                            const float* __restrict__ W1,
                                            const float* __restrict__ W2) {
    __shared__ char  buf[256 * 72 * 2];          // eas then h1s (aliased)
    __shared__ __half w1h[64][16];
    __shared__ __half w2s[64][72];
    __half (*eas)[24] = (__half(*)[24])buf;
    __half (*h1s)[72] = (__half(*)[72])buf;

    int t = threadIdx.x;
    for (int i = t; i < 512; i += 256) {
        w1h[i >> 3][i & 7] = __float2half(W1[i]);
        w1h[i >> 3][8 + (i & 7)] = __float2half(0.f);
    }
    for (int i = t; i < 4096; i += 256) w2s[i >> 6][i & 63] = __float2half(W2[i]);

    int base = blockIdx.x * 256;
    int w = t >> 5, l = t & 31;
    int p_own = g_pos[base + t];

    {
        float4 a0 = *(const float4*)&ea[(size_t)(base + t) * 8];
        float4 a1 = *(const float4*)&ea[(size_t)(base + t) * 8 + 4];
        __half2* er = (__half2*)&eas[t][0];
        er[0] = __floats2half2_rn(a0.x, a0.y);
        er[1] = __floats2half2_rn(a0.z, a0.w);
        er[2] = __floats2half2_rn(a1.x, a1.y);
        er[3] = __floats2half2_rn(a1.z, a1.w);
        __half2 z = __floats2half2_rn(0.f, 0.f);
        er[4] = z; er[5] = z; er[6] = z; er[7] = z;
    }
    __syncthreads();

    float c[2][8][4];
#pragma unroll
    for (int mt = 0; mt < 2; mt++)
#pragma unroll
        for (int nt = 0; nt < 8; nt++)
#pragma unroll
            for (int r = 0; r < 4; r++) c[mt][nt][r] = 0.f;

    {   // stage 1 MMA (K=16, zero-padded)
        int k0 = (l & 3) * 2;
        uint32_t a[2][4];
#pragma unroll
        for (int mt = 0; mt < 2; mt++) {
            int r = w * 32 + mt * 16 + (l >> 2);
            a[mt][0] = *(const uint32_t*)&eas[r][k0];
            a[mt][1] = *(const uint32_t*)&eas[r + 8][k0];
            a[mt][2] = *(const uint32_t*)&eas[r][k0 + 8];
            a[mt][3] = *(const uint32_t*)&eas[r + 8][k0 + 8];
        }
#pragma unroll
        for (int nt = 0; nt < 8; nt++) {
            int nr = nt * 8 + (l >> 2);
            uint32_t b0 = *(const uint32_t*)&w1h[nr][k0];
            uint32_t b1 = *(const uint32_t*)&w1h[nr][k0 + 8];
            mma16816(c[0][nt], a[0], b0, b1);
            mma16816(c[1][nt], a[1], b0, b1);
        }
    }
    __syncthreads();

#pragma unroll
    for (int mt = 0; mt < 2; mt++) {
        int m = w * 32 + mt * 16 + (l >> 2);
#pragma unroll
        for (int nt = 0; nt < 8; nt++) {
            int n = nt * 8 + (l & 3) * 2;
            float v0 = c[mt][nt][0], v1 = c[mt][nt][1];
            float v2 = c[mt][nt][2], v3 = c[mt][nt][3];
            v0 = v0 > 0.f ? v0 : 0.f; v1 = v1 > 0.f ? v1 : 0.f;
            v2 = v2 > 0.f ? v2 : 0.f; v3 = v3 > 0.f ? v3 : 0.f;
            *(__half2*)&h1s[m][n]     = __floats2half2_rn(v0, v1);
            *(__half2*)&h1s[m + 8][n] = __floats2half2_rn(v2, v3);
            c[mt][nt][0] = 0.f; c[mt][nt][1] = 0.f;
            c[mt][nt][2] = 0.f; c[mt][nt][3] = 0.f;
        }
    }
    __syncthreads();

#pragma unroll
    for (int kc = 0; kc < 4; kc++) {   // stage 2 MMA (K=64)
        int k0 = kc * 16 + (l & 3) * 2;
        uint32_t a[2][4];
#pragma unroll
        for (int mt = 0; mt < 2; mt++) {
            int r = w * 32 + mt * 16 + (l >> 2);
            a[mt][0] = *(const uint32_t*)&h1s[r][k0];
            a[mt][1] = *(const uint32_t*)&h1s[r + 8][k0];
            a[mt][2] = *(const uint32_t*)&h1s[r][k0 + 8];
            a[mt][3] = *(const uint32_t*)&h1s[r + 8][k0 + 8];
        }
#pragma unroll
        for (int nt = 0; nt < 8; nt++) {
            int nr = nt * 8 + (l >> 2);
            uint32_t b0 = *(const uint32_t*)&w2s[nr][k0];
            uint32_t b1 = *(const uint32_t*)&w2s[nr][k0 + 8];
            mma16816(c[0][nt], a[0], b0, b1);
            mma16816(c[1][nt], a[1], b0, b1);
        }
    }

#pragma unroll
    for (int mt = 0; mt < 2; mt++) {
        int srcl = mt * 16 + (l >> 2);
        int pos0 = __shfl_sync(0xffffffffu, p_own, srcl);
        int pos1 = __shfl_sync(0xffffffffu, p_own, srcl + 8);
        size_t row0 = (size_t)pos0 * 64;
        size_t row1 = (size_t)pos1 * 64;
#pragma unroll
        for (int nt = 0; nt < 8; nt++) {
            int n = nt * 8 + (l & 3) * 2;
            float v0 = c[mt][nt][0], v1 = c[mt][nt][1];
            float v2 = c[mt][nt][2], v3 = c[mt][nt][3];
            v0 = v0 > 0.f ? v0 : 0.f; v1 = v1 > 0.f ? v1 : 0.f;
            v2 = v2 > 0.f ? v2 : 0.f; v3 = v3 > 0.f ? v3 : 0.f;
            *(__half2*)&g_ew[row0 + n] = __floats2half2_rn(v0, v1);
            *(__half2*)&g_ew[row1 + n] = __floats2half2_rn(v2, v3);
        }
    }
}

// ---------------- degree / dinv (warp per node, half2, unroll 2) ----------------
__global__ void __launch_bounds__(256) k_deg() {
    int w = (blockIdx.x * blockDim.x + threadIdx.x) >> 5;
    int lane = threadIdx.x & 31;
    if (w >= NN) return;
    int s = g_off[w], e = g_off[w + 1];
    const __half2* ewv = (const __half2*)g_ew;
    float2 d0 = make_float2(1.f, 1.f);
    float2 d1 = make_float2(0.f, 0.f);
    int p = s;
    for (; p + 2 <= e; p += 2) {
        float2 v0 = __half22float2(ewv[(size_t)p * 32 + lane]);
        float2 v1 = __half22float2(ewv[(size_t)(p + 1) * 32 + lane]);
        d0.x += v0.x; d0.y += v0.y;
        d1.x += v1.x; d1.y += v1.y;
    }
    if (p < e) {
        float2 v0 = __half22float2(ewv[(size_t)p * 32 + lane]);
        d0.x += v0.x; d0.y += v0.y;
    }
    float2 r; r.x = rsqrtf(d0.x + d1.x); r.y = rsqrtf(d0.y + d1.y);
    ((float2*)g_dinv)[(size_t)w * 32 + lane] = r;
}

// ---------------- aggregation (warp per node), unroll 4, int4 src, fp16 y ----------------
__global__ void __launch_bounds__(256) k_agg(const float* __restrict__ bc) {
    int w = (blockIdx.x * blockDim.x + threadIdx.x) >> 5;
    int lane = threadIdx.x & 31;
    if (w >= NN) return;
    int s = g_off[w], e = g_off[w + 1];
    const __half2* yv  = (const __half2*)g_y;
    const __half2* ewv = (const __half2*)g_ew;
    float2 a0 = __half22float2(yv[(size_t)w * 32 + lane]);   // self loop
    float2 a1 = make_float2(0.f, 0.f);
    float2 a2 = make_float2(0.f, 0.f);
    float2 a3 = make_float2(0.f, 0.f);
    int p = s;
    for (; p < e && (p & 3); p++) {
        int s0 = g_src[p];
        float2 f0 = __half22float2(ewv[(size_t)p * 32 + lane]);
        float2 y0 = __half22float2(yv[(size_t)s0 * 32 + lane]);
        a0.x = fmaf(f0.x, y0.x, a0.x); a0.y = fmaf(f0.y, y0.y, a0.y);
    }
    for (; p + 4 <= e; p += 4) {
        int4 sv = *(const int4*)&g_src[p];
        __half2 h0 = ewv[(size_t)p * 32 + lane];
        __half2 h1 = ewv[(size_t)(p + 1) * 32 + lane];
        __half2 h2 = ewv[(size_t)(p + 2) * 32 + lane];
        __half2 h3 = ewv[(size_t)(p + 3) * 32 + lane];
        float2 y0 = __half22float2(yv[(size_t)sv.x * 32 + lane]);
        float2 y1 = __half22float2(yv[(size_t)sv.y * 32 + lane]);
        float2 y2 = __half22float2(yv[(size_t)sv.z * 32 + lane]);
        float2 y3 = __half22float2(yv[(size_t)sv.w * 32 + lane]);
        float2 f0 = __half22float2(h0), f1 = __half22float2(h1);
        float2 f2 = __half22float2(h2), f3 = __half22float2(h3);
        a0.x = fmaf(f0.x, y0.x, a0.x); a0.y = fmaf(f0.y, y0.y, a0.y);
        a1.x = fmaf(f1.x, y1.x, a1.x); a1.y = fmaf(f1.y, y1.y, a1.y);
        a2.x = fmaf(f2.x, y2.x, a2.x); a2.y = fmaf(f2.y, y2.y, a2.y);
        a3.x = fmaf(f3.x, y3.x, a3.x); a3.y = fmaf(f3.y, y3.y, a3.y);
    }
    for (; p < e; p++) {
        int s0 = g_src[p];
        float2 f0 = __half22float2(ewv[(size_t)p * 32 + lane]);
        float2 y0 = __half22float2(yv[(size_t)s0 * 32 + lane]);
        a0.x = fmaf(f0.x, y0.x, a0.x); a0.y = fmaf(f0.y, y0.y, a0.y);
    }
    float2 dv = ((const float2*)g_dinv)[(size_t)w * 32 + lane];
    float2 r;
    r.x = fmaf(dv.x, (a0.x + a1.x) + (a2.x + a3.x), bc[2 * lane]);
    r.y = fmaf(dv.y, (a0.y + a1.y) + (a2.y + a3.y), bc[2 * lane + 1]);
    ((float2*)g_hagg)[(size_t)w * 32 + lane] = r;
}

// ---------------- tensor-core GEMM: C[N,64] = A[N,128] @ W[64,128]^T ----------------
// K passes run A1 (hagg / xin hi) FIRST, A0 (xlin / xin lo) LAST, so As holds the
// xlin tile at epilogue time -> resid is read from smem (fp16), not gmem.
__global__ void __launch_bounds__(256) k_gemm(const float* __restrict__ xin,
                                              const float* __restrict__ W,
                                              const float* __restrict__ bias,
                                              int mode,
                                              const float* __restrict__ ywc,
                                              const float* __restrict__ Wo,
                                              float* __restrict__ out) {
    __shared__ __half As[128][72];
    __shared__ __half Bs[64][136];
    int t = threadIdx.x;
    {   // vectorized W -> Bs (fp16)
        const float4* W4 = (const float4*)W;
        for (int i = t; i < 2048; i += 256) {
            float4 v = W4[i];
            int r = i >> 5, c4 = (i & 31) * 4;
            Bs[r][c4]     = __float2half(v.x);
            Bs[r][c4 + 1] = __float2half(v.y);
            Bs[r][c4 + 2] = __float2half(v.z);
            Bs[r][c4 + 3] = __float2half(v.w);
        }
    }

    const float *A0, *A1; float* C; int lda; bool has_resid;
    if (mode == 0) { A0 = xin;    A1 = xin + 64; lda = 128; has_resid = false; C = g_xlin; }
    else           { A0 = g_xlin; A1 = g_hagg;   lda = 64;  has_resid = true;  C = g_h;    }

    int bm = blockIdx.x * 128;
    int w = t >> 5, l = t & 31;
    float c[8][4];
#pragma unroll
    for (int nt = 0; nt < 8; nt++)
#pragma unroll
        for (int r = 0; r < 4; r++) c[nt][r] = 0.f;

    int lrow = t >> 1, lc0 = (t & 1) * 32;
    bool lvalid = (bm + lrow) < NN;

#pragma unroll
    for (int pp = 0; pp < 2; pp++) {
        int pass = 1 - pp;                   // A1 first, A0 last (As keeps xlin tile)
        const float* A = pass ? A1 : A0;
        __syncthreads();
        const float* srcp = &A[(size_t)(bm + lrow) * lda + lc0];
#pragma unroll
        for (int ch = 0; ch < 4; ch++) {
            float4 v0 = make_float4(0.f, 0.f, 0.f, 0.f), v1 = v0;
            if (lvalid) {
                v0 = *(const float4*)&srcp[ch * 8];
                v1 = *(const float4*)&srcp[ch * 8 + 4];
            }
            __half2 h0 = __floats2half2_rn(v0.x, v0.y);
            __half2 h1 = __floats2half2_rn(v0.z, v0.w);
            __half2 h2 = __floats2half2_rn(v1.x, v1.y);
            __half2 h3 = __floats2half2_rn(v1.z, v1.w);
            uint4 pk;
            pk.x = *(uint32_t*)&h0; pk.y = *(uint32_t*)&h1;
            pk.z = *(uint32_t*)&h2; pk.w = *(uint32_t*)&h3;
            *(uint4*)&As[lrow][lc0 + ch * 8] = pk;
        }
        __syncthreads();
#pragma unroll
        for (int kc = 0; kc < 4; kc++) {
            int k0 = kc * 16 + (l & 3) * 2;
            int row = w * 16 + (l >> 2);
            uint32_t a[4];
            a[0] = *(const uint32_t*)&As[row][k0];
            a[1] = *(const uint32_t*)&As[row + 8][k0];
            a[2] = *(const uint32_t*)&As[row][k0 + 8];
            a[3] = *(const uint32_t*)&As[row + 8][k0 + 8];
            int kb = pass * 64 + k0;
#pragma unroll
            for (int nt = 0; nt < 8; nt++) {
                int nr = nt * 8 + (l >> 2);
                uint32_t b0 = *(const uint32_t*)&Bs[nr][kb];
                uint32_t b1 = *(const uint32_t*)&Bs[nr][kb + 8];
                mma16816(c[nt], a, b0, b1);
            }
        }
    }

    int m0 = bm + w * 16 + (l >> 2);
    int n0 = (l & 3) * 2;
    int trow = w * 16 + (l >> 2);            // tile row of m0 within As

    if (Wo) {
        float oacc[2] = {0.f, 0.f};
#pragma unroll
        for (int nt = 0; nt < 8; nt++) {
            int n = nt * 8 + n0;
            float wx0 = Wo[n], wx1 = Wo[n + 1];
            float wh0 = Wo[64 + n], wh1 = Wo[64 + n + 1];
#pragma unroll
            for (int rr = 0; rr < 2; rr++) {
                int m = m0 + rr * 8;
                if (m >= NN) continue;
                float2 rv = __half22float2(*(const __half2*)&As[trow + rr * 8][n]);
                float h0 = c[nt][rr * 2] + rv.x;
                float h1 = c[nt][rr * 2 + 1] + rv.y;
                h0 = h0 > 0.f ? h0 : 0.f;
                h1 = h1 > 0.f ? h1 : 0.f;
                oacc[rr] += rv.x * wx0 + rv.y * wx1 + h0 * wh0 + h1 * wh1;
            }
        }
#pragma unroll
        for (int rr = 0; rr < 2; rr++) {
            oacc[rr] += __shfl_xor_sync(0xffffffffu, oacc[rr], 1);
            oacc[rr] += __shfl_xor_sync(0xffffffffu, oacc[rr], 2);
        }
        if ((l & 3) == 0) {
            if (m0 < NN)     out[m0]     = oacc[0];
            if (m0 + 8 < NN) out[m0 + 8] = oacc[1];
        }
        return;
    }

#pragma unroll
    for (int nt = 0; nt < 8; nt++) {
        int n = nt * 8 + n0;
#pragma unroll
        for (int rr = 0; rr < 2; rr++) {
            int m = m0 + rr * 8;
            if (m >= NN) continue;
            float v0 = c[nt][rr * 2], v1 = c[nt][rr * 2 + 1];
            if (bias) { v0 += bias[n]; v1 += bias[n + 1]; }
            if (has_resid) {
                float2 rv = __half22float2(*(const __half2*)&As[trow + rr * 8][n]);
                v0 += rv.x; v1 += rv.y;
            }
            float2 ov; ov.x = v0; ov.y = v1;
            *(float2*)&C[(size_t)m * 64 + n] = ov;
            if (ywc) {
                float2 dv = *(const float2*)&g_dinv[(size_t)m * 64 + n];
                float r0 = v0 > 0.f ? v0 : 0.f;
                float r1 = v1 > 0.f ? v1 : 0.f;
                *(__half2*)&g_y[(size_t)m * 64 + n] =
                    __floats2half2_rn(dv.x * r0 * ywc[n], dv.y * r1 * ywc[n + 1]);
            }
        }
    }
}

// ---------------- host ----------------
extern "C" void kernel_launch(void* const* d_in, const int* in_sizes, int n_in,
                              void* d_out, int out_size) {
    const float* x  = (const float*)d_in[0];
    const int*   ei = (const int*)d_in[1];     // int32 [2, E]
    const float* ea = (const float*)d_in[2];
    const float* W1 = (const float*)d_in[3];
    const float* W2 = (const float*)d_in[4];
    const float* Wi = (const float*)d_in[5];
    const float* bi = (const float*)d_in[6];
    const float* wc = (const float*)d_in[7];
    const float* bc = (const float*)d_in[8];
    const float* Wl = (const float*)d_in[9];
    const float* Wo = (const float*)d_in[10];
    float* out = (float*)d_out;

    const int WPB = 8;
    k_zero<<<(NN + 1023) / 1024, 1024>>>();
    k_count<<<(NE + 255) / 256, 256>>>(ei);
    k_scan_sum<<<NBLK, 1024>>>();
    k_scan_top<<<1, 128>>>();
    k_scan_apply<<<NBLK, 1024>>>();
    k_fill<<<(NE + 255) / 256, 256>>>(ei);
    k_ew<<<NE / 256, 256>>>(ea, W1, W2);
    k_deg<<<(NN + WPB - 1) / WPB, 256>>>();
    k_gemm<<<(NN + 127) / 128, 256>>>(x, Wi, bi, 0, wc, nullptr, nullptr);
    for (int l = 0; l < 3; l++) {
        k_agg<<<(NN + WPB - 1) / WPB, 256>>>(bc + l * 64);
        k_gemm<<<(NN + 127) / 128, 256>>>(x, Wl + l * 64 * 128, nullptr, 1,
                                          l < 2 ? wc + (l + 1) * 64 : nullptr,
                                          l == 2 ? Wo : nullptr,
                                          l == 2 ? out : nullptr);
    }
}

// round 14
// speedup vs baseline: 1.3245x; 1.3245x over previous
#include <cuda_runtime.h>
#include <cuda_fp16.h>
#include <cstdint>

#define NN 100000
#define NE 1600000
#define H  64
#define SCAN_B 1024
#define NBLK ((NN + SCAN_B - 1) / SCAN_B)   // 98

// ---------------- scratch (device globals; no allocation) ----------------
__device__ __half g_ew[1600000ull * 64];  // edge weights fp16, CSR-slot order [E,64]
__device__ int    g_cnt[NN];
__device__ int    g_off[NN + 1];
__device__ int    g_cur[NN];
__device__ int    g_src[NE];              // CSR-slot -> source node
__device__ int    g_pos[NE];              // edge e -> CSR slot
__device__ int    g_bsum[NBLK];
__device__ int    g_boff[NBLK];
__device__ float  g_xlin[NN * H];
__device__ float  g_dinv[NN * H];
__device__ __half g_y[NN * H];            // fp16 gather operand
__device__ float  g_hagg[NN * H];
__device__ float  g_h[NN * H];

// ---------------- CSR build ----------------
__global__ void k_zero() {
    int i = blockIdx.x * blockDim.x + threadIdx.x;
    if (i < NN) g_cnt[i] = 0;
}

__global__ void k_count(const int* __restrict__ ei) {
    int e = blockIdx.x * blockDim.x + threadIdx.x;
    if (e < NE) {
        int c = ei[NE + e];
        if ((unsigned)c < (unsigned)NN) atomicAdd(&g_cnt[c], 1);
    }
}

// ---- hierarchical scan ----
__global__ void __launch_bounds__(1024) k_scan_sum() {
    __shared__ int s[1024];
    int t = threadIdx.x, b = blockIdx.x;
    int i = b * SCAN_B + t;
    s[t] = (i < NN) ? g_cnt[i] : 0;
    __syncthreads();
#pragma unroll
    for (int d = 512; d > 0; d >>= 1) {
        if (t < d) s[t] += s[t + d];
        __syncthreads();
    }
    if (t == 0) g_bsum[b] = s[0];
}

__global__ void __launch_bounds__(128) k_scan_top() {
    __shared__ int s[128];
    int t = threadIdx.x;
    int v = (t < NBLK) ? g_bsum[t] : 0;
    s[t] = v;
    __syncthreads();
#pragma unroll
    for (int d = 1; d < 128; d <<= 1) {
        int u = (t >= d) ? s[t - d] : 0;
        __syncthreads();
        s[t] += u;
        __syncthreads();
    }
    if (t < NBLK) g_boff[t] = s[t] - v;
    if (t == NBLK - 1) g_off[NN] = s[t];
}

__global__ void __launch_bounds__(1024) k_scan_apply() {
    __shared__ int s[1024];
    int t = threadIdx.x, b = blockIdx.x;
    int i = b * SCAN_B + t;
    int v = (i < NN) ? g_cnt[i] : 0;
    s[t] = v;
    __syncthreads();
#pragma unroll
    for (int d = 1; d < 1024; d <<= 1) {
        int u = (t >= d) ? s[t - d] : 0;
        __syncthreads();
        s[t] += u;
        __syncthreads();
    }
    if (i < NN) {
        int off = g_boff[b] + s[t] - v;
        g_off[i] = off;
        g_cur[i] = off;
    }
}

__global__ void k_fill(const int* __restrict__ ei) {
    int e = blockIdx.x * blockDim.x + threadIdx.x;
    if (e < NE) {
        int c = ei[NE + e];
        int r = ei[e];
        if ((unsigned)c >= (unsigned)NN || (unsigned)r >= (unsigned)NN) return;
        int p = atomicAdd(&g_cur[c], 1);
        g_src[p] = r;
        g_pos[e] = p;
    }
}

// ---------------- mma.m16n8k16 f32 += f16 x f16 ----------------
__device__ __forceinline__ void mma16816(float c[4], const uint32_t a[4],
                                         uint32_t b0, uint32_t b1) {
    asm volatile(
        "mma.sync.aligned.m16n8k16.row.col.f32.f16.f16.f32 "
        "{%0,%1,%2,%3}, {%4,%5,%6,%7}, {%8,%9}, {%0,%1,%2,%3};"
        : "+f"(c[0]), "+f"(c[1]), "+f"(c[2]), "+f"(c[3])
        : "r"(a[0]), "r"(a[1]), "r"(a[2]), "r"(a[3]), "r"(b0), "r"(b1));
}

// ---------------- edge MLP, BOTH stages on tensor cores ----------------
__global__ void __launch_bounds__(256) k_ew(const float* __restrict__ ea,
                                            const float* __restrict__ W1,
                                            const float* __restrict__ W2) {
    __shared__ char  buf[256 * 72 * 2];          // eas then h1s (aliased)
    __shared__ __half w1h[64][16];
    __shared__ __half w2s[64][72];
    __half (*eas)[24] = (__half(*)[24])buf;
    __half (*h1s)[72] = (__half(*)[72])buf;

    int t = threadIdx.x;
    for (int i = t; i < 512; i += 256) {
        w1h[i >> 3][i & 7] = __float2half(W1[i]);
        w1h[i >> 3][8 + (i & 7)] = __float2half(0.f);
    }
    for (int i = t; i < 4096; i += 256) w2s[i >> 6][i & 63] = __float2half(W2[i]);

    int base = blockIdx.x * 256;
    int w = t >> 5, l = t & 31;
    int p_own = g_pos[base + t];

    {
        float4 a0 = *(const float4*)&ea[(size_t)(base + t) * 8];
        float4 a1 = *(const float4*)&ea[(size_t)(base + t) * 8 + 4];
        __half2* er = (__half2*)&eas[t][0];
        er[0] = __floats2half2_rn(a0.x, a0.y);
        er[1] = __floats2half2_rn(a0.z, a0.w);
        er[2] = __floats2half2_rn(a1.x, a1.y);
        er[3] = __floats2half2_rn(a1.z, a1.w);
        __half2 z = __floats2half2_rn(0.f, 0.f);
        er[4] = z; er[5] = z; er[6] = z; er[7] = z;
    }
    __syncthreads();

    float c[2][8][4];
#pragma unroll
    for (int mt = 0; mt < 2; mt++)
#pragma unroll
        for (int nt = 0; nt < 8; nt++)
#pragma unroll
            for (int r = 0; r < 4; r++) c[mt][nt][r] = 0.f;

    {   // stage 1 MMA (K=16, zero-padded)
        int k0 = (l & 3) * 2;
        uint32_t a[2][4];
#pragma unroll
        for (int mt = 0; mt < 2; mt++) {
            int r = w * 32 + mt * 16 + (l >> 2);
            a[mt][0] = *(const uint32_t*)&eas[r][k0];
            a[mt][1] = *(const uint32_t*)&eas[r + 8][k0];
            a[mt][2] = *(const uint32_t*)&eas[r][k0 + 8];
            a[mt][3] = *(const uint32_t*)&eas[r + 8][k0 + 8];
        }
#pragma unroll
        for (int nt = 0; nt < 8; nt++) {
            int nr = nt * 8 + (l >> 2);
            uint32_t b0 = *(const uint32_t*)&w1h[nr][k0];
            uint32_t b1 = *(const uint32_t*)&w1h[nr][k0 + 8];
            mma16816(c[0][nt], a[0], b0, b1);
            mma16816(c[1][nt], a[1], b0, b1);
        }
    }
    __syncthreads();

#pragma unroll
    for (int mt = 0; mt < 2; mt++) {
        int m = w * 32 + mt * 16 + (l >> 2);
#pragma unroll
        for (int nt = 0; nt < 8; nt++) {
            int n = nt * 8 + (l & 3) * 2;
            float v0 = c[mt][nt][0], v1 = c[mt][nt][1];
            float v2 = c[mt][nt][2], v3 = c[mt][nt][3];
            v0 = v0 > 0.f ? v0 : 0.f; v1 = v1 > 0.f ? v1 : 0.f;
            v2 = v2 > 0.f ? v2 : 0.f; v3 = v3 > 0.f ? v3 : 0.f;
            *(__half2*)&h1s[m][n]     = __floats2half2_rn(v0, v1);
            *(__half2*)&h1s[m + 8][n] = __floats2half2_rn(v2, v3);
            c[mt][nt][0] = 0.f; c[mt][nt][1] = 0.f;
            c[mt][nt][2] = 0.f; c[mt][nt][3] = 0.f;
        }
    }
    __syncthreads();

#pragma unroll
    for (int kc = 0; kc < 4; kc++) {   // stage 2 MMA (K=64)
        int k0 = kc * 16 + (l & 3) * 2;
        uint32_t a[2][4];
#pragma unroll
        for (int mt = 0; mt < 2; mt++) {
            int r = w * 32 + mt * 16 + (l >> 2);
            a[mt][0] = *(const uint32_t*)&h1s[r][k0];
            a[mt][1] = *(const uint32_t*)&h1s[r + 8][k0];
            a[mt][2] = *(const uint32_t*)&h1s[r][k0 + 8];
            a[mt][3] = *(const uint32_t*)&h1s[r + 8][k0 + 8];
        }
#pragma unroll
        for (int nt = 0; nt < 8; nt++) {
            int nr = nt * 8 + (l >> 2);
            uint32_t b0 = *(const uint32_t*)&w2s[nr][k0];
            uint32_t b1 = *(const uint32_t*)&w2s[nr][k0 + 8];
            mma16816(c[0][nt], a[0], b0, b1);
            mma16816(c[1][nt], a[1], b0, b1);
        }
    }

#pragma unroll
    for (int mt = 0; mt < 2; mt++) {
        int srcl = mt * 16 + (l >> 2);
        int pos0 = __shfl_sync(0xffffffffu, p_own, srcl);
        int pos1 = __shfl_sync(0xffffffffu, p_own, srcl + 8);
        size_t row0 = (size_t)pos0 * 64;
        size_t row1 = (size_t)pos1 * 64;
#pragma unroll
        for (int nt = 0; nt < 8; nt++) {
            int n = nt * 8 + (l & 3) * 2;
            float v0 = c[mt][nt][0], v1 = c[mt][nt][1];
            float v2 = c[mt][nt][2], v3 = c[mt][nt][3];
            v0 = v0 > 0.f ? v0 : 0.f; v1 = v1 > 0.f ? v1 : 0.f;
            v2 = v2 > 0.f ? v2 : 0.f; v3 = v3 > 0.f ? v3 : 0.f;
            *(__half2*)&g_ew[row0 + n] = __floats2half2_rn(v0, v1);
            *(__half2*)&g_ew[row1 + n] = __floats2half2_rn(v2, v3);
        }
    }
}

// ---------------- degree / dinv (warp per node, half2, unroll 2) ----------------
__global__ void __launch_bounds__(256) k_deg() {
    int w = (blockIdx.x * blockDim.x + threadIdx.x) >> 5;
    int lane = threadIdx.x & 31;
    if (w >= NN) return;
    int s = g_off[w], e = g_off[w + 1];
    const __half2* ewv = (const __half2*)g_ew;
    float2 d0 = make_float2(1.f, 1.f);
    float2 d1 = make_float2(0.f, 0.f);
    int p = s;
    for (; p + 2 <= e; p += 2) {
        float2 v0 = __half22float2(ewv[(size_t)p * 32 + lane]);
        float2 v1 = __half22float2(ewv[(size_t)(p + 1) * 32 + lane]);
        d0.x += v0.x; d0.y += v0.y;
        d1.x += v1.x; d1.y += v1.y;
    }
    if (p < e) {
        float2 v0 = __half22float2(ewv[(size_t)p * 32 + lane]);
        d0.x += v0.x; d0.y += v0.y;
    }
    float2 r; r.x = rsqrtf(d0.x + d1.x); r.y = rsqrtf(d0.y + d1.y);
    ((float2*)g_dinv)[(size_t)w * 32 + lane] = r;
}

// ---------------- aggregation (warp per node), unroll 4, int4 src, fp16 y ----------------
__global__ void __launch_bounds__(256) k_agg(const float* __restrict__ bc) {
    int w = (blockIdx.x * blockDim.x + threadIdx.x) >> 5;
    int lane = threadIdx.x & 31;
    if (w >= NN) return;
    int s = g_off[w], e = g_off[w + 1];
    const __half2* yv  = (const __half2*)g_y;
    const __half2* ewv = (const __half2*)g_ew;
    float2 a0 = __half22float2(yv[(size_t)w * 32 + lane]);   // self loop
    float2 a1 = make_float2(0.f, 0.f);
    float2 a2 = make_float2(0.f, 0.f);
    float2 a3 = make_float2(0.f, 0.f);
    int p = s;
    for (; p < e && (p & 3); p++) {
        int s0 = g_src[p];
        float2 f0 = __half22float2(ewv[(size_t)p * 32 + lane]);
        float2 y0 = __half22float2(yv[(size_t)s0 * 32 + lane]);
        a0.x = fmaf(f0.x, y0.x, a0.x); a0.y = fmaf(f0.y, y0.y, a0.y);
    }
    for (; p + 4 <= e; p += 4) {
        int4 sv = *(const int4*)&g_src[p];
        __half2 h0 = ewv[(size_t)p * 32 + lane];
        __half2 h1 = ewv[(size_t)(p + 1) * 32 + lane];
        __half2 h2 = ewv[(size_t)(p + 2) * 32 + lane];
        __half2 h3 = ewv[(size_t)(p + 3) * 32 + lane];
        float2 y0 = __half22float2(yv[(size_t)sv.x * 32 + lane]);
        float2 y1 = __half22float2(yv[(size_t)sv.y * 32 + lane]);
        float2 y2 = __half22float2(yv[(size_t)sv.z * 32 + lane]);
        float2 y3 = __half22float2(yv[(size_t)sv.w * 32 + lane]);
        float2 f0 = __half22float2(h0), f1 = __half22float2(h1);
        float2 f2 = __half22float2(h2), f3 = __half22float2(h3);
        a0.x = fmaf(f0.x, y0.x, a0.x); a0.y = fmaf(f0.y, y0.y, a0.y);
        a1.x = fmaf(f1.x, y1.x, a1.x); a1.y = fmaf(f1.y, y1.y, a1.y);
        a2.x = fmaf(f2.x, y2.x, a2.x); a2.y = fmaf(f2.y, y2.y, a2.y);
        a3.x = fmaf(f3.x, y3.x, a3.x); a3.y = fmaf(f3.y, y3.y, a3.y);
    }
    for (; p < e; p++) {
        int s0 = g_src[p];
        float2 f0 = __half22float2(ewv[(size_t)p * 32 + lane]);
        float2 y0 = __half22float2(yv[(size_t)s0 * 32 + lane]);
        a0.x = fmaf(f0.x, y0.x, a0.x); a0.y = fmaf(f0.y, y0.y, a0.y);
    }
    float2 dv = ((const float2*)g_dinv)[(size_t)w * 32 + lane];
    float2 r;
    r.x = fmaf(dv.x, (a0.x + a1.x) + (a2.x + a3.x), bc[2 * lane]);
    r.y = fmaf(dv.y, (a0.y + a1.y) + (a2.y + a3.y), bc[2 * lane + 1]);
    ((float2*)g_hagg)[(size_t)w * 32 + lane] = r;
}

// ---------------- tensor-core GEMM: C[N,64] = A[N,128] @ W[64,128]^T ----------------
__global__ void __launch_bounds__(256) k_gemm(const float* __restrict__ xin,
                                              const float* __restrict__ W,
                                              const float* __restrict__ bias,
                                              int mode,
                                              const float* __restrict__ ywc,
                                              const float* __restrict__ Wo,
                                              float* __restrict__ out) {
    __shared__ __half As[128][72];
    __shared__ __half Bs[64][136];
    int t = threadIdx.x;
    {   // vectorized W -> Bs (fp16)
        const float4* W4 = (const float4*)W;
        for (int i = t; i < 2048; i += 256) {
            float4 v = W4[i];
            int r = i >> 5, c4 = (i & 31) * 4;
            Bs[r][c4]     = __float2half(v.x);
            Bs[r][c4 + 1] = __float2half(v.y);
            Bs[r][c4 + 2] = __float2half(v.z);
            Bs[r][c4 + 3] = __float2half(v.w);
        }
    }

    const float *A0, *A1, *resid; float* C; int lda;
    if (mode == 0) { A0 = xin;    A1 = xin + 64; lda = 128; resid = 0;      C = g_xlin; }
    else           { A0 = g_xlin; A1 = g_hagg;   lda = 64;  resid = g_xlin; C = g_h;    }

    int bm = blockIdx.x * 128;
    int w = t >> 5, l = t & 31;
    float c[8][4];
#pragma unroll
    for (int nt = 0; nt < 8; nt++)
#pragma unroll
        for (int r = 0; r < 4; r++) c[nt][r] = 0.f;

    int lrow = t >> 1, lc0 = (t & 1) * 32;
    bool lvalid = (bm + lrow) < NN;

#pragma unroll
    for (int pass = 0; pass < 2; pass++) {
        const float* A = pass ? A1 : A0;
        __syncthreads();
        const float* srcp = &A[(size_t)(bm + lrow) * lda + lc0];
#pragma unroll
        for (int ch = 0; ch < 4; ch++) {
            float4 v0 = make_float4(0.f, 0.f, 0.f, 0.f), v1 = v0;
            if (lvalid) {
                v0 = *(const float4*)&srcp[ch * 8];
                v1 = *(const float4*)&srcp[ch * 8 + 4];
            }
            __half2 h0 = __floats2half2_rn(v0.x, v0.y);
            __half2 h1 = __floats2half2_rn(v0.z, v0.w);
            __half2 h2 = __floats2half2_rn(v1.x, v1.y);
            __half2 h3 = __floats2half2_rn(v1.z, v1.w);
            uint4 pk;
            pk.x = *(uint32_t*)&h0; pk.y = *(uint32_t*)&h1;
            pk.z = *(uint32_t*)&h2; pk.w = *(uint32_t*)&h3;
            *(uint4*)&As[lrow][lc0 + ch * 8] = pk;
        }
        __syncthreads();
#pragma unroll
        for (int kc = 0; kc < 4; kc++) {
            int k0 = kc * 16 + (l & 3) * 2;
            int row = w * 16 + (l >> 2);
            uint32_t a[4];
            a[0] = *(const uint32_t*)&As[row][k0];
            a[1] = *(const uint32_t*)&As[row + 8][k0];
            a[2] = *(const uint32_t*)&As[row][k0 + 8];
            a[3] = *(const uint32_t*)&As[row + 8][k0 + 8];
            int kb = pass * 64 + k0;
#pragma unroll
            for (int nt = 0; nt < 8; nt++) {
                int nr = nt * 8 + (l >> 2);
                uint32_t b0 = *(const uint32_t*)&Bs[nr][kb];
                uint32_t b1 = *(const uint32_t*)&Bs[nr][kb + 8];
                mma16816(c[nt], a, b0, b1);
            }
        }
    }

    int m0 = bm + w * 16 + (l >> 2);
    int n0 = (l & 3) * 2;

    if (Wo) {
        float oacc[2] = {0.f, 0.f};
#pragma unroll
        for (int nt = 0; nt < 8; nt++) {
            int n = nt * 8 + n0;
            float wx0 = Wo[n], wx1 = Wo[n + 1];
            float wh0 = Wo[64 + n], wh1 = Wo[64 + n + 1];
#pragma unroll
            for (int rr = 0; rr < 2; rr++) {
                int m = m0 + rr * 8;
                if (m >= NN) continue;
                float2 rv = *(const float2*)&resid[(size_t)m * 64 + n];
                float h0 = c[nt][rr * 2] + rv.x;
                float h1 = c[nt][rr * 2 + 1] + rv.y;
                h0 = h0 > 0.f ? h0 : 0.f;
                h1 = h1 > 0.f ? h1 : 0.f;
                oacc[rr] += rv.x * wx0 + rv.y * wx1 + h0 * wh0 + h1 * wh1;
            }
        }
#pragma unroll
        for (int rr = 0; rr < 2; rr++) {
            oacc[rr] += __shfl_xor_sync(0xffffffffu, oacc[rr], 1);
            oacc[rr] += __shfl_xor_sync(0xffffffffu, oacc[rr], 2);
        }
        if ((l & 3) == 0) {
            if (m0 < NN)     out[m0]     = oacc[0];
            if (m0 + 8 < NN) out[m0 + 8] = oacc[1];
        }
        return;
    }

#pragma unroll
    for (int nt = 0; nt < 8; nt++) {
        int n = nt * 8 + n0;
#pragma unroll
        for (int rr = 0; rr < 2; rr++) {
            int m = m0 + rr * 8;
            if (m >= NN) continue;
            float v0 = c[nt][rr * 2], v1 = c[nt][rr * 2 + 1];
            if (bias) { v0 += bias[n]; v1 += bias[n + 1]; }
            if (resid) {
                float2 rv = *(const float2*)&resid[(size_t)m * 64 + n];
                v0 += rv.x; v1 += rv.y;
            }
            float2 ov; ov.x = v0; ov.y = v1;
            *(float2*)&C[(size_t)m * 64 + n] = ov;
            if (ywc) {
                float2 dv = *(const float2*)&g_dinv[(size_t)m * 64 + n];
                float r0 = v0 > 0.f ? v0 : 0.f;
                float r1 = v1 > 0.f ? v1 : 0.f;
                *(__half2*)&g_y[(size_t)m * 64 + n] =
                    __floats2half2_rn(dv.x * r0 * ywc[n], dv.y * r1 * ywc[n + 1]);
            }
        }
    }
}

// ---------------- host ----------------
extern "C" void kernel_launch(void* const* d_in, const int* in_sizes, int n_in,
                              void* d_out, int out_size) {
    const float* x  = (const float*)d_in[0];
    const int*   ei = (const int*)d_in[1];     // int32 [2, E]
    const float* ea = (const float*)d_in[2];
    const float* W1 = (const float*)d_in[3];
    const float* W2 = (const float*)d_in[4];
    const float* Wi = (const float*)d_in[5];
    const float* bi = (const float*)d_in[6];
    const float* wc = (const float*)d_in[7];
    const float* bc = (const float*)d_in[8];
    const float* Wl = (const float*)d_in[9];
    const float* Wo = (const float*)d_in[10];
    float* out = (float*)d_out;

    const int WPB = 8;
    k_zero<<<(NN + 1023) / 1024, 1024>>>();
    k_count<<<(NE + 255) / 256, 256>>>(ei);
    k_scan_sum<<<NBLK, 1024>>>();
    k_scan_top<<<1, 128>>>();
    k_scan_apply<<<NBLK, 1024>>>();
    k_fill<<<(NE + 255) / 256, 256>>>(ei);
    k_ew<<<NE / 256, 256>>>(ea, W1, W2);
    k_deg<<<(NN + WPB - 1) / WPB, 256>>>();
    k_gemm<<<(NN + 127) / 128, 256>>>(x, Wi, bi, 0, wc, nullptr, nullptr);
    for (int l = 0; l < 3; l++) {
        k_agg<<<(NN + WPB - 1) / WPB, 256>>>(bc + l * 64);
        k_gemm<<<(NN + 127) / 128, 256>>>(x, Wl + l * 64 * 128, nullptr, 1,
                                          l < 2 ? wc + (l + 1) * 64 : nullptr,
                                          l == 2 ? Wo : nullptr,
                                          l == 2 ? out : nullptr);
    }
}

// round 15
// speedup vs baseline: 1.4429x; 1.0894x over previous
#include <cuda_runtime.h>
#include <cuda_fp16.h>
#include <cstdint>

#define NN 100000
#define NE 1600000
#define H  64
#define SCAN_B 1024
#define NBLK ((NN + SCAN_B - 1) / SCAN_B)   // 98

// ---------------- scratch (device globals; no allocation) ----------------
__device__ __half g_ew[1600000ull * 64];  // edge weights fp16, CSR-slot order [E,64]
__device__ int    g_cnt[NN];
__device__ int    g_off[NN + 1];
__device__ int    g_cur[NN];
__device__ int    g_src[NE];              // CSR-slot -> source node
__device__ int    g_pos[NE];              // edge e -> CSR slot
__device__ int    g_bsum[NBLK];
__device__ int    g_boff[NBLK];
__device__ float  g_xlin[NN * H];
__device__ float  g_dinv[NN * H];
__device__ __half g_y[NN * H];            // fp16 gather operand
__device__ __half g_hagg[NN * H];         // fp16 (GEMM rounded it anyway)
__device__ float  g_h[NN * H];

// ---------------- CSR build ----------------
__global__ void k_zero() {
    int i = blockIdx.x * blockDim.x + threadIdx.x;
    if (i < NN) g_cnt[i] = 0;
}

__global__ void k_count(const int* __restrict__ ei) {
    int e = blockIdx.x * blockDim.x + threadIdx.x;
    if (e < NE) {
        int c = ei[NE + e];
        if ((unsigned)c < (unsigned)NN) atomicAdd(&g_cnt[c], 1);
    }
}

// ---- hierarchical scan ----
__global__ void __launch_bounds__(1024) k_scan_sum() {
    __shared__ int s[1024];
    int t = threadIdx.x, b = blockIdx.x;
    int i = b * SCAN_B + t;
    s[t] = (i < NN) ? g_cnt[i] : 0;
    __syncthreads();
#pragma unroll
    for (int d = 512; d > 0; d >>= 1) {
        if (t < d) s[t] += s[t + d];
        __syncthreads();
    }
    if (t == 0) g_bsum[b] = s[0];
}

__global__ void __launch_bounds__(128) k_scan_top() {
    __shared__ int s[128];
    int t = threadIdx.x;
    int v = (t < NBLK) ? g_bsum[t] : 0;
    s[t] = v;
    __syncthreads();
#pragma unroll
    for (int d = 1; d < 128; d <<= 1) {
        int u = (t >= d) ? s[t - d] : 0;
        __syncthreads();
        s[t] += u;
        __syncthreads();
    }
    if (t < NBLK) g_boff[t] = s[t] - v;
    if (t == NBLK - 1) g_off[NN] = s[t];
}

__global__ void __launch_bounds__(1024) k_scan_apply() {
    __shared__ int s[1024];
    int t = threadIdx.x, b = blockIdx.x;
    int i = b * SCAN_B + t;
    int v = (i < NN) ? g_cnt[i] : 0;
    s[t] = v;
    __syncthreads();
#pragma unroll
    for (int d = 1; d < 1024; d <<= 1) {
        int u = (t >= d) ? s[t - d] : 0;
        __syncthreads();
        s[t] += u;
        __syncthreads();
    }
    if (i < NN) {
        int off = g_boff[b] + s[t] - v;
        g_off[i] = off;
        g_cur[i] = off;
    }
}

__global__ void k_fill(const int* __restrict__ ei) {
    int e = blockIdx.x * blockDim.x + threadIdx.x;
    if (e < NE) {
        int c = ei[NE + e];
        int r = ei[e];
        if ((unsigned)c >= (unsigned)NN || (unsigned)r >= (unsigned)NN) return;
        int p = atomicAdd(&g_cur[c], 1);
        g_src[p] = r;
        g_pos[e] = p;
    }
}

// ---------------- mma.m16n8k16 f32 += f16 x f16 ----------------
__device__ __forceinline__ void mma16816(float c[4], const uint32_t a[4],
                                         uint32_t b0, uint32_t b1) {
    asm volatile(
        "mma.sync.aligned.m16n8k16.row.col.f32.f16.f16.f32 "
        "{%0,%1,%2,%3}, {%4,%5,%6,%7}, {%8,%9}, {%0,%1,%2,%3};"
        : "+f"(c[0]), "+f"(c[1]), "+f"(c[2]), "+f"(c[3])
        : "r"(a[0]), "r"(a[1]), "r"(a[2]), "r"(a[3]), "r"(b0), "r"(b1));
}

// ---------------- edge MLP, BOTH stages on tensor cores ----------------
// Epilogue stages rows in smem, then scatter-copies full 128B rows coalesced
// (8 lanes x 16B per row -> 1 wavefront/row instead of 8).
__global__ void __launch_bounds__(256) k_ew(const float* __restrict__ ea,
                                            const float* __restrict__ W1,
                                            const float* __restrict__ W2) {
    __shared__ char  buf[256 * 72 * 2];          // eas / h1s / result rows (aliased)
    __shared__ __half w1h[64][8];                // 1024 B
    __shared__ __half w2s[64][72];               // 9216 B
    __shared__ int    poss[256];                 // 1024 B   (total 48128 B)
    __half (*eas)[24] = (__half(*)[24])buf;
    __half (*h1s)[72] = (__half(*)[72])buf;

    int t = threadIdx.x;
    for (int i = t; i < 512; i += 256) w1h[i >> 3][i & 7] = __float2half(W1[i]);
    for (int i = t; i < 4096; i += 256) w2s[i >> 6][i & 63] = __float2half(W2[i]);

    int base = blockIdx.x * 256;
    int w = t >> 5, l = t & 31;
    poss[t] = g_pos[base + t];

    {
        float4 a0 = *(const float4*)&ea[(size_t)(base + t) * 8];
        float4 a1 = *(const float4*)&ea[(size_t)(base + t) * 8 + 4];
        __half2* er = (__half2*)&eas[t][0];
        er[0] = __floats2half2_rn(a0.x, a0.y);
        er[1] = __floats2half2_rn(a0.z, a0.w);
        er[2] = __floats2half2_rn(a1.x, a1.y);
        er[3] = __floats2half2_rn(a1.z, a1.w);
        __half2 z = __floats2half2_rn(0.f, 0.f);
        er[4] = z; er[5] = z; er[6] = z; er[7] = z;
    }
    __syncthreads();

    float c[2][8][4];
#pragma unroll
    for (int mt = 0; mt < 2; mt++)
#pragma unroll
        for (int nt = 0; nt < 8; nt++)
#pragma unroll
            for (int r = 0; r < 4; r++) c[mt][nt][r] = 0.f;

    {   // stage 1 MMA: K=16, upper K-half is zero (B operand literal 0)
        int k0 = (l & 3) * 2;
        uint32_t a[2][4];
#pragma unroll
        for (int mt = 0; mt < 2; mt++) {
            int r = w * 32 + mt * 16 + (l >> 2);
            a[mt][0] = *(const uint32_t*)&eas[r][k0];
            a[mt][1] = *(const uint32_t*)&eas[r + 8][k0];
            a[mt][2] = *(const uint32_t*)&eas[r][k0 + 8];
            a[mt][3] = *(const uint32_t*)&eas[r + 8][k0 + 8];
        }
#pragma unroll
        for (int nt = 0; nt < 8; nt++) {
            int nr = nt * 8 + (l >> 2);
            uint32_t b0 = *(const uint32_t*)&w1h[nr][k0];
            mma16816(c[0][nt], a[0], b0, 0u);
            mma16816(c[1][nt], a[1], b0, 0u);
        }
    }
    __syncthreads();

#pragma unroll
    for (int mt = 0; mt < 2; mt++) {
        int m = w * 32 + mt * 16 + (l >> 2);
#pragma unroll
        for (int nt = 0; nt < 8; nt++) {
            int n = nt * 8 + (l & 3) * 2;
            float v0 = c[mt][nt][0], v1 = c[mt][nt][1];
            float v2 = c[mt][nt][2], v3 = c[mt][nt][3];
            v0 = v0 > 0.f ? v0 : 0.f; v1 = v1 > 0.f ? v1 : 0.f;
            v2 = v2 > 0.f ? v2 : 0.f; v3 = v3 > 0.f ? v3 : 0.f;
            *(__half2*)&h1s[m][n]     = __floats2half2_rn(v0, v1);
            *(__half2*)&h1s[m + 8][n] = __floats2half2_rn(v2, v3);
            c[mt][nt][0] = 0.f; c[mt][nt][1] = 0.f;
            c[mt][nt][2] = 0.f; c[mt][nt][3] = 0.f;
        }
    }
    __syncthreads();

#pragma unroll
    for (int kc = 0; kc < 4; kc++) {   // stage 2 MMA (K=64)
        int k0 = kc * 16 + (l & 3) * 2;
        uint32_t a[2][4];
#pragma unroll
        for (int mt = 0; mt < 2; mt++) {
            int r = w * 32 + mt * 16 + (l >> 2);
            a[mt][0] = *(const uint32_t*)&h1s[r][k0];
            a[mt][1] = *(const uint32_t*)&h1s[r + 8][k0];
            a[mt][2] = *(const uint32_t*)&h1s[r][k0 + 8];
            a[mt][3] = *(const uint32_t*)&h1s[r + 8][k0 + 8];
        }
#pragma unroll
        for (int nt = 0; nt < 8; nt++) {
            int nr = nt * 8 + (l >> 2);
            uint32_t b0 = *(const uint32_t*)&w2s[nr][k0];
            uint32_t b1 = *(const uint32_t*)&w2s[nr][k0 + 8];
            mma16816(c[0][nt], a[0], b0, b1);
            mma16816(c[1][nt], a[1], b0, b1);
        }
    }
    __syncthreads();   // all h1s MMA reads done before result rows overwrite buf

    // stage results into smem rows (relu + fp16)
#pragma unroll
    for (int mt = 0; mt < 2; mt++) {
        int m = w * 32 + mt * 16 + (l >> 2);
#pragma unroll
        for (int nt = 0; nt < 8; nt++) {
            int n = nt * 8 + (l & 3) * 2;
            float v0 = c[mt][nt][0], v1 = c[mt][nt][1];
            float v2 = c[mt][nt][2], v3 = c[mt][nt][3];
            v0 = v0 > 0.f ? v0 : 0.f; v1 = v1 > 0.f ? v1 : 0.f;
            v2 = v2 > 0.f ? v2 : 0.f; v3 = v3 > 0.f ? v3 : 0.f;
            *(__half2*)&h1s[m][n]     = __floats2half2_rn(v0, v1);
            *(__half2*)&h1s[m + 8][n] = __floats2half2_rn(v2, v3);
        }
    }
    __syncthreads();

    // coalesced scatter: 8 lanes x 16B per 128B row, 4 rows per warp-instr
#pragma unroll
    for (int i = 0; i < 8; i++) {
        int row = (t >> 3) + i * 32;
        int col = t & 7;
        uint4 v = *(const uint4*)&h1s[row][col * 8];
        *(uint4*)&g_ew[(size_t)poss[row] * 64 + col * 8] = v;
    }
}

// ---------------- degree / dinv (warp per node, half2, unroll 2) ----------------
__global__ void __launch_bounds__(256) k_deg() {
    int w = (blockIdx.x * blockDim.x + threadIdx.x) >> 5;
    int lane = threadIdx.x & 31;
    if (w >= NN) return;
    int s = g_off[w], e = g_off[w + 1];
    const __half2* ewv = (const __half2*)g_ew;
    float2 d0 = make_float2(1.f, 1.f);
    float2 d1 = make_float2(0.f, 0.f);
    int p = s;
    for (; p + 2 <= e; p += 2) {
        float2 v0 = __half22float2(ewv[(size_t)p * 32 + lane]);
        float2 v1 = __half22float2(ewv[(size_t)(p + 1) * 32 + lane]);
        d0.x += v0.x; d0.y += v0.y;
        d1.x += v1.x; d1.y += v1.y;
    }
    if (p < e) {
        float2 v0 = __half22float2(ewv[(size_t)p * 32 + lane]);
        d0.x += v0.x; d0.y += v0.y;
    }
    float2 r; r.x = rsqrtf(d0.x + d1.x); r.y = rsqrtf(d0.y + d1.y);
    ((float2*)g_dinv)[(size_t)w * 32 + lane] = r;
}

// ---------------- aggregation (warp per node), unroll 4, int4 src, fp16 y ----------------
__global__ void __launch_bounds__(256) k_agg(const float* __restrict__ bc) {
    int w = (blockIdx.x * blockDim.x + threadIdx.x) >> 5;
    int lane = threadIdx.x & 31;
    if (w >= NN) return;
    int s = g_off[w], e = g_off[w + 1];
    const __half2* yv  = (const __half2*)g_y;
    const __half2* ewv = (const __half2*)g_ew;
    float2 a0 = __half22float2(yv[(size_t)w * 32 + lane]);   // self loop
    float2 a1 = make_float2(0.f, 0.f);
    float2 a2 = make_float2(0.f, 0.f);
    float2 a3 = make_float2(0.f, 0.f);
    int p = s;
    for (; p < e && (p & 3); p++) {
        int s0 = g_src[p];
        float2 f0 = __half22float2(ewv[(size_t)p * 32 + lane]);
        float2 y0 = __half22float2(yv[(size_t)s0 * 32 + lane]);
        a0.x = fmaf(f0.x, y0.x, a0.x); a0.y = fmaf(f0.y, y0.y, a0.y);
    }
    for (; p + 4 <= e; p += 4) {
        int4 sv = *(const int4*)&g_src[p];
        __half2 h0 = ewv[(size_t)p * 32 + lane];
        __half2 h1 = ewv[(size_t)(p + 1) * 32 + lane];
        __half2 h2 = ewv[(size_t)(p + 2) * 32 + lane];
        __half2 h3 = ewv[(size_t)(p + 3) * 32 + lane];
        float2 y0 = __half22float2(yv[(size_t)sv.x * 32 + lane]);
        float2 y1 = __half22float2(yv[(size_t)sv.y * 32 + lane]);
        float2 y2 = __half22float2(yv[(size_t)sv.z * 32 + lane]);
        float2 y3 = __half22float2(yv[(size_t)sv.w * 32 + lane]);
        float2 f0 = __half22float2(h0), f1 = __half22float2(h1);
        float2 f2 = __half22float2(h2), f3 = __half22float2(h3);
        a0.x = fmaf(f0.x, y0.x, a0.x); a0.y = fmaf(f0.y, y0.y, a0.y);
        a1.x = fmaf(f1.x, y1.x, a1.x); a1.y = fmaf(f1.y, y1.y, a1.y);
        a2.x = fmaf(f2.x, y2.x, a2.x); a2.y = fmaf(f2.y, y2.y, a2.y);
        a3.x = fmaf(f3.x, y3.x, a3.x); a3.y = fmaf(f3.y, y3.y, a3.y);
    }
    for (; p < e; p++) {
        int s0 = g_src[p];
        float2 f0 = __half22float2(ewv[(size_t)p * 32 + lane]);
        float2 y0 = __half22float2(yv[(size_t)s0 * 32 + lane]);
        a0.x = fmaf(f0.x, y0.x, a0.x); a0.y = fmaf(f0.y, y0.y, a0.y);
    }
    float2 dv = ((const float2*)g_dinv)[(size_t)w * 32 + lane];
    float rx = fmaf(dv.x, (a0.x + a1.x) + (a2.x + a3.x), bc[2 * lane]);
    float ry = fmaf(dv.y, (a0.y + a1.y) + (a2.y + a3.y), bc[2 * lane + 1]);
    ((__half2*)g_hagg)[(size_t)w * 32 + lane] = __floats2half2_rn(rx, ry);
}

// ---------------- tensor-core GEMM: C[N,64] = A[N,128] @ W[64,128]^T ----------------
// mode 0: A = xin fp32 (lda 128), bias=bi, C=g_xlin
// mode 1: pass0 A = g_xlin fp32, pass1 A = g_hagg fp16 (raw copy), resid=g_xlin, C=g_h
__global__ void __launch_bounds__(256) k_gemm(const float* __restrict__ xin,
                                              const float* __restrict__ W,
                                              const float* __restrict__ bias,
                                              int mode,
                                              const float* __restrict__ ywc,
                                              const float* __restrict__ Wo,
                                              float* __restrict__ out) {
    __shared__ __half As[128][72];
    __shared__ __half Bs[64][136];
    int t = threadIdx.x;
    {   // vectorized W -> Bs (fp16)
        const float4* W4 = (const float4*)W;
        for (int i = t; i < 2048; i += 256) {
            float4 v = W4[i];
            int r = i >> 5, c4 = (i & 31) * 4;
            Bs[r][c4]     = __float2half(v.x);
            Bs[r][c4 + 1] = __float2half(v.y);
            Bs[r][c4 + 2] = __float2half(v.z);
            Bs[r][c4 + 3] = __float2half(v.w);
        }
    }

    const float *A0, *A1, *resid; float* C; int lda;
    if (mode == 0) { A0 = xin;    A1 = xin + 64; lda = 128; resid = 0;      C = g_xlin; }
    else           { A0 = g_xlin; A1 = nullptr;  lda = 64;  resid = g_xlin; C = g_h;    }

    int bm = blockIdx.x * 128;
    int w = t >> 5, l = t & 31;
    float c[8][4];
#pragma unroll
    for (int nt = 0; nt < 8; nt++)
#pragma unroll
        for (int r = 0; r < 4; r++) c[nt][r] = 0.f;

    int lrow = t >> 1, lc0 = (t & 1) * 32;
    bool lvalid = (bm + lrow) < NN;

#pragma unroll
    for (int pass = 0; pass < 2; pass++) {
        __syncthreads();
        if (mode == 1 && pass == 1) {
            // hagg is already fp16: raw 16B copies, no conversion
            const __half* srcp = g_hagg + (size_t)(bm + lrow) * 64 + lc0;
#pragma unroll
            for (int ch = 0; ch < 4; ch++) {
                uint4 pk = make_uint4(0u, 0u, 0u, 0u);
                if (lvalid) pk = *(const uint4*)&srcp[ch * 8];
                *(uint4*)&As[lrow][lc0 + ch * 8] = pk;
            }
        } else {
            const float* A = pass ? A1 : A0;
            const float* srcp = &A[(size_t)(bm + lrow) * lda + lc0];
#pragma unroll
            for (int ch = 0; ch < 4; ch++) {
                float4 v0 = make_float4(0.f, 0.f, 0.f, 0.f), v1 = v0;
                if (lvalid) {
                    v0 = *(const float4*)&srcp[ch * 8];
                    v1 = *(const float4*)&srcp[ch * 8 + 4];
                }
                __half2 h0 = __floats2half2_rn(v0.x, v0.y);
                __half2 h1 = __floats2half2_rn(v0.z, v0.w);
                __half2 h2 = __floats2half2_rn(v1.x, v1.y);
                __half2 h3 = __floats2half2_rn(v1.z, v1.w);
                uint4 pk;
                pk.x = *(uint32_t*)&h0; pk.y = *(uint32_t*)&h1;
                pk.z = *(uint32_t*)&h2; pk.w = *(uint32_t*)&h3;
                *(uint4*)&As[lrow][lc0 + ch * 8] = pk;
            }
        }
        __syncthreads();
#pragma unroll
        for (int kc = 0; kc < 4; kc++) {
            int k0 = kc * 16 + (l & 3) * 2;
            int row = w * 16 + (l >> 2);
            uint32_t a[4];
            a[0] = *(const uint32_t*)&As[row][k0];
            a[1] = *(const uint32_t*)&As[row + 8][k0];
            a[2] = *(const uint32_t*)&As[row][k0 + 8];
            a[3] = *(const uint32_t*)&As[row + 8][k0 + 8];
            int kb = pass * 64 + k0;
#pragma unroll
            for (int nt = 0; nt < 8; nt++) {
                int nr = nt * 8 + (l >> 2);
                uint32_t b0 = *(const uint32_t*)&Bs[nr][kb];
                uint32_t b1 = *(const uint32_t*)&Bs[nr][kb + 8];
                mma16816(c[nt], a, b0, b1);
            }
        }
    }

    int m0 = bm + w * 16 + (l >> 2);
    int n0 = (l & 3) * 2;

    if (Wo) {
        float oacc[2] = {0.f, 0.f};
#pragma unroll
        for (int nt = 0; nt < 8; nt++) {
            int n = nt * 8 + n0;
            float wx0 = Wo[n], wx1 = Wo[n + 1];
            float wh0 = Wo[64 + n], wh1 = Wo[64 + n + 1];
#pragma unroll
            for (int rr = 0; rr < 2; rr++) {
                int m = m0 + rr * 8;
                if (m >= NN) continue;
                float2 rv = *(const float2*)&resid[(size_t)m * 64 + n];
                float h0 = c[nt][rr * 2] + rv.x;
                float h1 = c[nt][rr * 2 + 1] + rv.y;
                h0 = h0 > 0.f ? h0 : 0.f;
                h1 = h1 > 0.f ? h1 : 0.f;
                oacc[rr] += rv.x * wx0 + rv.y * wx1 + h0 * wh0 + h1 * wh1;
            }
        }
#pragma unroll
        for (int rr = 0; rr < 2; rr++) {
            oacc[rr] += __shfl_xor_sync(0xffffffffu, oacc[rr], 1);
            oacc[rr] += __shfl_xor_sync(0xffffffffu, oacc[rr], 2);
        }
        if ((l & 3) == 0) {
            if (m0 < NN)     out[m0]     = oacc[0];
            if (m0 + 8 < NN) out[m0 + 8] = oacc[1];
        }
        return;
    }

#pragma unroll
    for (int nt = 0; nt < 8; nt++) {
        int n = nt * 8 + n0;
#pragma unroll
        for (int rr = 0; rr < 2; rr++) {
            int m = m0 + rr * 8;
            if (m >= NN) continue;
            float v0 = c[nt][rr * 2], v1 = c[nt][rr * 2 + 1];
            if (bias) { v0 += bias[n]; v1 += bias[n + 1]; }
            if (resid) {
                float2 rv = *(const float2*)&resid[(size_t)m * 64 + n];
                v0 += rv.x; v1 += rv.y;
            }
            float2 ov; ov.x = v0; ov.y = v1;
            *(float2*)&C[(size_t)m * 64 + n] = ov;
            if (ywc) {
                float2 dv = *(const float2*)&g_dinv[(size_t)m * 64 + n];
                float r0 = v0 > 0.f ? v0 : 0.f;
                float r1 = v1 > 0.f ? v1 : 0.f;
                *(__half2*)&g_y[(size_t)m * 64 + n] =
                    __floats2half2_rn(dv.x * r0 * ywc[n], dv.y * r1 * ywc[n + 1]);
            }
        }
    }
}

// ---------------- host ----------------
extern "C" void kernel_launch(void* const* d_in, const int* in_sizes, int n_in,
                              void* d_out, int out_size) {
    const float* x  = (const float*)d_in[0];
    const int*   ei = (const int*)d_in[1];     // int32 [2, E]
    const float* ea = (const float*)d_in[2];
    const float* W1 = (const float*)d_in[3];
    const float* W2 = (const float*)d_in[4];
    const float* Wi = (const float*)d_in[5];
    const float* bi = (const float*)d_in[6];
    const float* wc = (const float*)d_in[7];
    const float* bc = (const float*)d_in[8];
    const float* Wl = (const float*)d_in[9];
    const float* Wo = (const float*)d_in[10];
    float* out = (float*)d_out;

    const int WPB = 8;
    k_zero<<<(NN + 1023) / 1024, 1024>>>();
    k_count<<<(NE + 255) / 256, 256>>>(ei);
    k_scan_sum<<<NBLK, 1024>>>();
    k_scan_top<<<1, 128>>>();
    k_scan_apply<<<NBLK, 1024>>>();
    k_fill<<<(NE + 255) / 256, 256>>>(ei);
    k_ew<<<NE / 256, 256>>>(ea, W1, W2);
    k_deg<<<(NN + WPB - 1) / WPB, 256>>>();
    k_gemm<<<(NN + 127) / 128, 256>>>(x, Wi, bi, 0, wc, nullptr, nullptr);
    for (int l = 0; l < 3; l++) {
        k_agg<<<(NN + WPB - 1) / WPB, 256>>>(bc + l * 64);
        k_gemm<<<(NN + 127) / 128, 256>>>(x, Wl + l * 64 * 128, nullptr, 1,
                                          l < 2 ? wc + (l + 1) * 64 : nullptr,
                                          l == 2 ? Wo : nullptr,
                                          l == 2 ? out : nullptr);
    }
}

// round 16
// speedup vs baseline: 1.4580x; 1.0105x over previous
#include <cuda_runtime.h>
#include <cuda_fp16.h>
#include <cstdint>

#define NN 100000
#define NE 1600000
#define H  64
#define SCAN_B 1024
#define NBLK ((NN + SCAN_B - 1) / SCAN_B)   // 98

// ---------------- scratch (device globals; no allocation) ----------------
__device__ __half g_ew[1600000ull * 64];  // edge weights fp16, CSR-slot order [E,64]
__device__ int    g_cnt[NN];
__device__ int    g_off[NN + 1];
__device__ int    g_cur[NN];
__device__ int    g_src[NE];              // CSR-slot -> source node
__device__ int    g_pos[NE];              // edge e -> CSR slot
__device__ int    g_bsum[NBLK];
__device__ int    g_boff[NBLK];
__device__ float  g_xlin[NN * H];
__device__ float  g_dinv[NN * H];
__device__ __half g_y[NN * H];            // fp16 gather operand (keep L2-resident)
__device__ __half g_hagg[NN * H];         // fp16
__device__ float  g_h[NN * H];

// ---------------- CSR build ----------------
__global__ void k_zero() {
    int i = blockIdx.x * blockDim.x + threadIdx.x;
    if (i < NN) g_cnt[i] = 0;
}

__global__ void k_count(const int* __restrict__ ei) {
    int e = blockIdx.x * blockDim.x + threadIdx.x;
    if (e < NE) {
        int c = ei[NE + e];
        if ((unsigned)c < (unsigned)NN) atomicAdd(&g_cnt[c], 1);
    }
}

// ---- hierarchical scan ----
__global__ void __launch_bounds__(1024) k_scan_sum() {
    __shared__ int s[1024];
    int t = threadIdx.x, b = blockIdx.x;
    int i = b * SCAN_B + t;
    s[t] = (i < NN) ? g_cnt[i] : 0;
    __syncthreads();
#pragma unroll
    for (int d = 512; d > 0; d >>= 1) {
        if (t < d) s[t] += s[t + d];
        __syncthreads();
    }
    if (t == 0) g_bsum[b] = s[0];
}

__global__ void __launch_bounds__(128) k_scan_top() {
    __shared__ int s[128];
    int t = threadIdx.x;
    int v = (t < NBLK) ? g_bsum[t] : 0;
    s[t] = v;
    __syncthreads();
#pragma unroll
    for (int d = 1; d < 128; d <<= 1) {
        int u = (t >= d) ? s[t - d] : 0;
        __syncthreads();
        s[t] += u;
        __syncthreads();
    }
    if (t < NBLK) g_boff[t] = s[t] - v;
    if (t == NBLK - 1) g_off[NN] = s[t];
}

__global__ void __launch_bounds__(1024) k_scan_apply() {
    __shared__ int s[1024];
    int t = threadIdx.x, b = blockIdx.x;
    int i = b * SCAN_B + t;
    int v = (i < NN) ? g_cnt[i] : 0;
    s[t] = v;
    __syncthreads();
#pragma unroll
    for (int d = 1; d < 1024; d <<= 1) {
        int u = (t >= d) ? s[t - d] : 0;
        __syncthreads();
        s[t] += u;
        __syncthreads();
    }
    if (i < NN) {
        int off = g_boff[b] + s[t] - v;
        g_off[i] = off;
        g_cur[i] = off;
    }
}

__global__ void k_fill(const int* __restrict__ ei) {
    int e = blockIdx.x * blockDim.x + threadIdx.x;
    if (e < NE) {
        int c = ei[NE + e];
        int r = ei[e];
        if ((unsigned)c >= (unsigned)NN || (unsigned)r >= (unsigned)NN) return;
        int p = atomicAdd(&g_cur[c], 1);
        g_src[p] = r;
        g_pos[e] = p;
    }
}

// ---------------- mma.m16n8k16 f32 += f16 x f16 ----------------
__device__ __forceinline__ void mma16816(float c[4], const uint32_t a[4],
                                         uint32_t b0, uint32_t b1) {
    asm volatile(
        "mma.sync.aligned.m16n8k16.row.col.f32.f16.f16.f32 "
        "{%0,%1,%2,%3}, {%4,%5,%6,%7}, {%8,%9}, {%0,%1,%2,%3};"
        : "+f"(c[0]), "+f"(c[1]), "+f"(c[2]), "+f"(c[3])
        : "r"(a[0]), "r"(a[1]), "r"(a[2]), "r"(a[3]), "r"(b0), "r"(b1));
}

// ---------------- edge MLP, BOTH stages on tensor cores ----------------
// Final scatter uses __stcs (evict-first): ew has no L2 reuse before deg.
__global__ void __launch_bounds__(256) k_ew(const float* __restrict__ ea,
                                            const float* __restrict__ W1,
                                            const float* __restrict__ W2) {
    __shared__ char  buf[256 * 72 * 2];          // eas / h1s / result rows (aliased)
    __shared__ __half w1h[64][8];
    __shared__ __half w2s[64][72];
    __shared__ int    poss[256];
    __half (*eas)[24] = (__half(*)[24])buf;
    __half (*h1s)[72] = (__half(*)[72])buf;

    int t = threadIdx.x;
    for (int i = t; i < 512; i += 256) w1h[i >> 3][i & 7] = __float2half(W1[i]);
    for (int i = t; i < 4096; i += 256) w2s[i >> 6][i & 63] = __float2half(W2[i]);

    int base = blockIdx.x * 256;
    int w = t >> 5, l = t & 31;
    poss[t] = g_pos[base + t];

    {
        float4 a0 = *(const float4*)&ea[(size_t)(base + t) * 8];
        float4 a1 = *(const float4*)&ea[(size_t)(base + t) * 8 + 4];
        __half2* er = (__half2*)&eas[t][0];
        er[0] = __floats2half2_rn(a0.x, a0.y);
        er[1] = __floats2half2_rn(a0.z, a0.w);
        er[2] = __floats2half2_rn(a1.x, a1.y);
        er[3] = __floats2half2_rn(a1.z, a1.w);
        __half2 z = __floats2half2_rn(0.f, 0.f);
        er[4] = z; er[5] = z; er[6] = z; er[7] = z;
    }
    __syncthreads();

    float c[2][8][4];
#pragma unroll
    for (int mt = 0; mt < 2; mt++)
#pragma unroll
        for (int nt = 0; nt < 8; nt++)
#pragma unroll
            for (int r = 0; r < 4; r++) c[mt][nt][r] = 0.f;

    {   // stage 1 MMA: K=16, upper K-half is zero (B operand literal 0)
        int k0 = (l & 3) * 2;
        uint32_t a[2][4];
#pragma unroll
        for (int mt = 0; mt < 2; mt++) {
            int r = w * 32 + mt * 16 + (l >> 2);
            a[mt][0] = *(const uint32_t*)&eas[r][k0];
            a[mt][1] = *(const uint32_t*)&eas[r + 8][k0];
            a[mt][2] = *(const uint32_t*)&eas[r][k0 + 8];
            a[mt][3] = *(const uint32_t*)&eas[r + 8][k0 + 8];
        }
#pragma unroll
        for (int nt = 0; nt < 8; nt++) {
            int nr = nt * 8 + (l >> 2);
            uint32_t b0 = *(const uint32_t*)&w1h[nr][k0];
            mma16816(c[0][nt], a[0], b0, 0u);
            mma16816(c[1][nt], a[1], b0, 0u);
        }
    }
    __syncthreads();

#pragma unroll
    for (int mt = 0; mt < 2; mt++) {
        int m = w * 32 + mt * 16 + (l >> 2);
#pragma unroll
        for (int nt = 0; nt < 8; nt++) {
            int n = nt * 8 + (l & 3) * 2;
            float v0 = c[mt][nt][0], v1 = c[mt][nt][1];
            float v2 = c[mt][nt][2], v3 = c[mt][nt][3];
            v0 = v0 > 0.f ? v0 : 0.f; v1 = v1 > 0.f ? v1 : 0.f;
            v2 = v2 > 0.f ? v2 : 0.f; v3 = v3 > 0.f ? v3 : 0.f;
            *(__half2*)&h1s[m][n]     = __floats2half2_rn(v0, v1);
            *(__half2*)&h1s[m + 8][n] = __floats2half2_rn(v2, v3);
            c[mt][nt][0] = 0.f; c[mt][nt][1] = 0.f;
            c[mt][nt][2] = 0.f; c[mt][nt][3] = 0.f;
        }
    }
    __syncthreads();

#pragma unroll
    for (int kc = 0; kc < 4; kc++) {   // stage 2 MMA (K=64)
        int k0 = kc * 16 + (l & 3) * 2;
        uint32_t a[2][4];
#pragma unroll
        for (int mt = 0; mt < 2; mt++) {
            int r = w * 32 + mt * 16 + (l >> 2);
            a[mt][0] = *(const uint32_t*)&h1s[r][k0];
            a[mt][1] = *(const uint32_t*)&h1s[r + 8][k0];
            a[mt][2] = *(const uint32_t*)&h1s[r][k0 + 8];
            a[mt][3] = *(const uint32_t*)&h1s[r + 8][k0 + 8];
        }
#pragma unroll
        for (int nt = 0; nt < 8; nt++) {
            int nr = nt * 8 + (l >> 2);
            uint32_t b0 = *(const uint32_t*)&w2s[nr][k0];
            uint32_t b1 = *(const uint32_t*)&w2s[nr][k0 + 8];
            mma16816(c[0][nt], a[0], b0, b1);
            mma16816(c[1][nt], a[1], b0, b1);
        }
    }
    __syncthreads();   // all h1s MMA reads done before result rows overwrite buf

    // stage results into smem rows (relu + fp16)
#pragma unroll
    for (int mt = 0; mt < 2; mt++) {
        int m = w * 32 + mt * 16 + (l >> 2);
#pragma unroll
        for (int nt = 0; nt < 8; nt++) {
            int n = nt * 8 + (l & 3) * 2;
            float v0 = c[mt][nt][0], v1 = c[mt][nt][1];
            float v2 = c[mt][nt][2], v3 = c[mt][nt][3];
            v0 = v0 > 0.f ? v0 : 0.f; v1 = v1 > 0.f ? v1 : 0.f;
            v2 = v2 > 0.f ? v2 : 0.f; v3 = v3 > 0.f ? v3 : 0.f;
            *(__half2*)&h1s[m][n]     = __floats2half2_rn(v0, v1);
            *(__half2*)&h1s[m + 8][n] = __floats2half2_rn(v2, v3);
        }
    }
    __syncthreads();

    // coalesced scatter: 8 lanes x 16B per 128B row, streaming stores
#pragma unroll
    for (int i = 0; i < 8; i++) {
        int row = (t >> 3) + i * 32;
        int col = t & 7;
        uint4 v = *(const uint4*)&h1s[row][col * 8];
        __stcs((uint4*)&g_ew[(size_t)poss[row] * 64 + col * 8], v);
    }
}

// ---------------- degree / dinv (warp per node, half2, unroll 2, ldcs) ----------------
__global__ void __launch_bounds__(256) k_deg() {
    int w = (blockIdx.x * blockDim.x + threadIdx.x) >> 5;
    int lane = threadIdx.x & 31;
    if (w >= NN) return;
    int s = g_off[w], e = g_off[w + 1];
    const __half2* ewv = (const __half2*)g_ew;
    float2 d0 = make_float2(1.f, 1.f);
    float2 d1 = make_float2(0.f, 0.f);
    int p = s;
    for (; p + 2 <= e; p += 2) {
        float2 v0 = __half22float2(__ldcs(&ewv[(size_t)p * 32 + lane]));
        float2 v1 = __half22float2(__ldcs(&ewv[(size_t)(p + 1) * 32 + lane]));
        d0.x += v0.x; d0.y += v0.y;
        d1.x += v1.x; d1.y += v1.y;
    }
    if (p < e) {
        float2 v0 = __half22float2(__ldcs(&ewv[(size_t)p * 32 + lane]));
        d0.x += v0.x; d0.y += v0.y;
    }
    float2 r; r.x = rsqrtf(d0.x + d1.x); r.y = rsqrtf(d0.y + d1.y);
    ((float2*)g_dinv)[(size_t)w * 32 + lane] = r;
}

// ---------------- aggregation (warp per node), unroll 4, int4 src, fp16 y, ldcs ew ----------------
__global__ void __launch_bounds__(256) k_agg(const float* __restrict__ bc) {
    int w = (blockIdx.x * blockDim.x + threadIdx.x) >> 5;
    int lane = threadIdx.x & 31;
    if (w >= NN) return;
    int s = g_off[w], e = g_off[w + 1];
    const __half2* yv  = (const __half2*)g_y;
    const __half2* ewv = (const __half2*)g_ew;
    float2 a0 = __half22float2(yv[(size_t)w * 32 + lane]);   // self loop
    float2 a1 = make_float2(0.f, 0.f);
    float2 a2 = make_float2(0.f, 0.f);
    float2 a3 = make_float2(0.f, 0.f);
    int p = s;
    for (; p < e && (p & 3); p++) {
        int s0 = g_src[p];
        float2 f0 = __half22float2(__ldcs(&ewv[(size_t)p * 32 + lane]));
        float2 y0 = __half22float2(yv[(size_t)s0 * 32 + lane]);
        a0.x = fmaf(f0.x, y0.x, a0.x); a0.y = fmaf(f0.y, y0.y, a0.y);
    }
    for (; p + 4 <= e; p += 4) {
        int4 sv = *(const int4*)&g_src[p];
        __half2 h0 = __ldcs(&ewv[(size_t)p * 32 + lane]);
        __half2 h1 = __ldcs(&ewv[(size_t)(p + 1) * 32 + lane]);
        __half2 h2 = __ldcs(&ewv[(size_t)(p + 2) * 32 + lane]);
        __half2 h3 = __ldcs(&ewv[(size_t)(p + 3) * 32 + lane]);
        float2 y0 = __half22float2(yv[(size_t)sv.x * 32 + lane]);
        float2 y1 = __half22float2(yv[(size_t)sv.y * 32 + lane]);
        float2 y2 = __half22float2(yv[(size_t)sv.z * 32 + lane]);
        float2 y3 = __half22float2(yv[(size_t)sv.w * 32 + lane]);
        float2 f0 = __half22float2(h0), f1 = __half22float2(h1);
        float2 f2 = __half22float2(h2), f3 = __half22float2(h3);
        a0.x = fmaf(f0.x, y0.x, a0.x); a0.y = fmaf(f0.y, y0.y, a0.y);
        a1.x = fmaf(f1.x, y1.x, a1.x); a1.y = fmaf(f1.y, y1.y, a1.y);
        a2.x = fmaf(f2.x, y2.x, a2.x); a2.y = fmaf(f2.y, y2.y, a2.y);
        a3.x = fmaf(f3.x, y3.x, a3.x); a3.y = fmaf(f3.y, y3.y, a3.y);
    }
    for (; p < e; p++) {
        int s0 = g_src[p];
        float2 f0 = __half22float2(__ldcs(&ewv[(size_t)p * 32 + lane]));
        float2 y0 = __half22float2(yv[(size_t)s0 * 32 + lane]);
        a0.x = fmaf(f0.x, y0.x, a0.x); a0.y = fmaf(f0.y, y0.y, a0.y);
    }
    float2 dv = ((const float2*)g_dinv)[(size_t)w * 32 + lane];
    float rx = fmaf(dv.x, (a0.x + a1.x) + (a2.x + a3.x), bc[2 * lane]);
    float ry = fmaf(dv.y, (a0.y + a1.y) + (a2.y + a3.y), bc[2 * lane + 1]);
    ((__half2*)g_hagg)[(size_t)w * 32 + lane] = __floats2half2_rn(rx, ry);
}

// ---------------- tensor-core GEMM: C[N,64] = A[N,128] @ W[64,128]^T ----------------
// mode 0: A = xin fp32 (lda 128), bias=bi, C=g_xlin
// mode 1: pass0 A = g_xlin fp32, pass1 A = g_hagg fp16 (raw copy), resid=g_xlin, C=g_h
__global__ void __launch_bounds__(256) k_gemm(const float* __restrict__ xin,
                                              const float* __restrict__ W,
                                              const float* __restrict__ bias,
                                              int mode,
                                              const float* __restrict__ ywc,
                                              const float* __restrict__ Wo,
                                              float* __restrict__ out) {
    __shared__ __half As[128][72];
    __shared__ __half Bs[64][136];
    int t = threadIdx.x;
    {   // vectorized W -> Bs (fp16)
        const float4* W4 = (const float4*)W;
        for (int i = t; i < 2048; i += 256) {
            float4 v = W4[i];
            int r = i >> 5, c4 = (i & 31) * 4;
            Bs[r][c4]     = __float2half(v.x);
            Bs[r][c4 + 1] = __float2half(v.y);
            Bs[r][c4 + 2] = __float2half(v.z);
            Bs[r][c4 + 3] = __float2half(v.w);
        }
    }

    const float *A0, *A1, *resid; float* C; int lda;
    if (mode == 0) { A0 = xin;    A1 = xin + 64; lda = 128; resid = 0;      C = g_xlin; }
    else           { A0 = g_xlin; A1 = nullptr;  lda = 64;  resid = g_xlin; C = g_h;    }

    int bm = blockIdx.x * 128;
    int w = t >> 5, l = t & 31;
    float c[8][4];
#pragma unroll
    for (int nt = 0; nt < 8; nt++)
#pragma unroll
        for (int r = 0; r < 4; r++) c[nt][r] = 0.f;

    int lrow = t >> 1, lc0 = (t & 1) * 32;
    bool lvalid = (bm + lrow) < NN;

#pragma unroll
    for (int pass = 0; pass < 2; pass++) {
        __syncthreads();
        if (mode == 1 && pass == 1) {
            const __half* srcp = g_hagg + (size_t)(bm + lrow) * 64 + lc0;
#pragma unroll
            for (int ch = 0; ch < 4; ch++) {
                uint4 pk = make_uint4(0u, 0u, 0u, 0u);
                if (lvalid) pk = *(const uint4*)&srcp[ch * 8];
                *(uint4*)&As[lrow][lc0 + ch * 8] = pk;
            }
        } else {
            const float* A = pass ? A1 : A0;
            const float* srcp = &A[(size_t)(bm + lrow) * lda + lc0];
#pragma unroll
            for (int ch = 0; ch < 4; ch++) {
                float4 v0 = make_float4(0.f, 0.f, 0.f, 0.f), v1 = v0;
                if (lvalid) {
                    v0 = *(const float4*)&srcp[ch * 8];
                    v1 = *(const float4*)&srcp[ch * 8 + 4];
                }
                __half2 h0 = __floats2half2_rn(v0.x, v0.y);
                __half2 h1 = __floats2half2_rn(v0.z, v0.w);
                __half2 h2 = __floats2half2_rn(v1.x, v1.y);
                __half2 h3 = __floats2half2_rn(v1.z, v1.w);
                uint4 pk;
                pk.x = *(uint32_t*)&h0; pk.y = *(uint32_t*)&h1;
                pk.z = *(uint32_t*)&h2; pk.w = *(uint32_t*)&h3;
                *(uint4*)&As[lrow][lc0 + ch * 8] = pk;
            }
        }
        __syncthreads();
#pragma unroll
        for (int kc = 0; kc < 4; kc++) {
            int k0 = kc * 16 + (l & 3) * 2;
            int row = w * 16 + (l >> 2);
            uint32_t a[4];
            a[0] = *(const uint32_t*)&As[row][k0];
            a[1] = *(const uint32_t*)&As[row + 8][k0];
            a[2] = *(const uint32_t*)&As[row][k0 + 8];
            a[3] = *(const uint32_t*)&As[row + 8][k0 + 8];
            int kb = pass * 64 + k0;
#pragma unroll
            for (int nt = 0; nt < 8; nt++) {
                int nr = nt * 8 + (l >> 2);
                uint32_t b0 = *(const uint32_t*)&Bs[nr][kb];
                uint32_t b1 = *(const uint32_t*)&Bs[nr][kb + 8];
                mma16816(c[nt], a, b0, b1);
            }
        }
    }

    int m0 = bm + w * 16 + (l >> 2);
    int n0 = (l & 3) * 2;

    if (Wo) {
        float oacc[2] = {0.f, 0.f};
#pragma unroll
        for (int nt = 0; nt < 8; nt++) {
            int n = nt * 8 + n0;
            float wx0 = Wo[n], wx1 = Wo[n + 1];
            float wh0 = Wo[64 + n], wh1 = Wo[64 + n + 1];
#pragma unroll
            for (int rr = 0; rr < 2; rr++) {
                int m = m0 + rr * 8;
                if (m >= NN) continue;
                float2 rv = *(const float2*)&resid[(size_t)m * 64 + n];
                float h0 = c[nt][rr * 2] + rv.x;
                float h1 = c[nt][rr * 2 + 1] + rv.y;
                h0 = h0 > 0.f ? h0 : 0.f;
                h1 = h1 > 0.f ? h1 : 0.f;
                oacc[rr] += rv.x * wx0 + rv.y * wx1 + h0 * wh0 + h1 * wh1;
            }
        }
#pragma unroll
        for (int rr = 0; rr < 2; rr++) {
            oacc[rr] += __shfl_xor_sync(0xffffffffu, oacc[rr], 1);
            oacc[rr] += __shfl_xor_sync(0xffffffffu, oacc[rr], 2);
        }
        if ((l & 3) == 0) {
            if (m0 < NN)     out[m0]     = oacc[0];
            if (m0 + 8 < NN) out[m0 + 8] = oacc[1];
        }
        return;
    }

#pragma unroll
    for (int nt = 0; nt < 8; nt++) {
        int n = nt * 8 + n0;
#pragma unroll
        for (int rr = 0; rr < 2; rr++) {
            int m = m0 + rr * 8;
            if (m >= NN) continue;
            float v0 = c[nt][rr * 2], v1 = c[nt][rr * 2 + 1];
            if (bias) { v0 += bias[n]; v1 += bias[n + 1]; }
            if (resid) {
                float2 rv = *(const float2*)&resid[(size_t)m * 64 + n];
                v0 += rv.x; v1 += rv.y;
            }
            float2 ov; ov.x = v0; ov.y = v1;
            *(float2*)&C[(size_t)m * 64 + n] = ov;
            if (ywc) {
                float2 dv = *(const float2*)&g_dinv[(size_t)m * 64 + n];
                float r0 = v0 > 0.f ? v0 : 0.f;
                float r1 = v1 > 0.f ? v1 : 0.f;
                *(__half2*)&g_y[(size_t)m * 64 + n] =
                    __floats2half2_rn(dv.x * r0 * ywc[n], dv.y * r1 * ywc[n + 1]);
            }
        }
    }
}

// ---------------- host ----------------
extern "C" void kernel_launch(void* const* d_in, const int* in_sizes, int n_in,
                              void* d_out, int out_size) {
    const float* x  = (const float*)d_in[0];
    const int*   ei = (const int*)d_in[1];     // int32 [2, E]
    const float* ea = (const float*)d_in[2];
    const float* W1 = (const float*)d_in[3];
    const float* W2 = (const float*)d_in[4];
    const float* Wi = (const float*)d_in[5];
    const float* bi = (const float*)d_in[6];
    const float* wc = (const float*)d_in[7];
    const float* bc = (const float*)d_in[8];
    const float* Wl = (const float*)d_in[9];
    const float* Wo = (const float*)d_in[10];
    float* out = (float*)d_out;

    const int WPB = 8;
    k_zero<<<(NN + 1023) / 1024, 1024>>>();
    k_count<<<(NE + 255) / 256, 256>>>(ei);
    k_scan_sum<<<NBLK, 1024>>>();
    k_scan_top<<<1, 128>>>();
    k_scan_apply<<<NBLK, 1024>>>();
    k_fill<<<(NE + 255) / 256, 256>>>(ei);
    k_ew<<<NE / 256, 256>>>(ea, W1, W2);
    k_deg<<<(NN + WPB - 1) / WPB, 256>>>();
    k_gemm<<<(NN + 127) / 128, 256>>>(x, Wi, bi, 0, wc, nullptr, nullptr);
    for (int l = 0; l < 3; l++) {
        k_agg<<<(NN + WPB - 1) / WPB, 256>>>(bc + l * 64);
        k_gemm<<<(NN + 127) / 128, 256>>>(x, Wl + l * 64 * 128, nullptr, 1,
                                          l < 2 ? wc + (l + 1) * 64 : nullptr,
                                          l == 2 ? Wo : nullptr,
                                          l == 2 ? out : nullptr);
    }
}

// round 17
// speedup vs baseline: 1.6051x; 1.1009x over previous
#include <cuda_runtime.h>
#include <cuda_fp16.h>
#include <cstdint>

#define NN 100000
#define NE 1600000
#define H  64
#define SCAN_B 1024
#define NBLK ((NN + SCAN_B - 1) / SCAN_B)   // 98

// ---------------- scratch (device globals; no allocation) ----------------
__device__ __half g_ew[1600000ull * 64];  // edge weights fp16, CSR-slot order [E,64]
__device__ int    g_cnt[NN];
__device__ int    g_off[NN + 1];
__device__ int    g_cur[NN];
__device__ int    g_src[NE];              // CSR-slot -> source node
__device__ int    g_pos[NE];              // edge e -> CSR slot
__device__ int    g_bsum[NBLK];
__device__ int    g_boff[NBLK];
__device__ __half g_xlin[NN * H];         // fp16 (GEMM rounds it anyway; resid cost measured ok)
__device__ float  g_dinv[NN * H];
__device__ __half g_y[NN * H];            // fp16 gather operand
__device__ __half g_hagg[NN * H];         // fp16

// ---------------- CSR build ----------------
__global__ void k_zero() {
    int i = blockIdx.x * blockDim.x + threadIdx.x;
    if (i < NN) g_cnt[i] = 0;
}

__global__ void k_count(const int* __restrict__ ei) {
    int e = blockIdx.x * blockDim.x + threadIdx.x;
    if (e < NE) {
        int c = ei[NE + e];
        if ((unsigned)c < (unsigned)NN) atomicAdd(&g_cnt[c], 1);
    }
}

// ---- hierarchical scan ----
__global__ void __launch_bounds__(1024) k_scan_sum() {
    __shared__ int s[1024];
    int t = threadIdx.x, b = blockIdx.x;
    int i = b * SCAN_B + t;
    s[t] = (i < NN) ? g_cnt[i] : 0;
    __syncthreads();
#pragma unroll
    for (int d = 512; d > 0; d >>= 1) {
        if (t < d) s[t] += s[t + d];
        __syncthreads();
    }
    if (t == 0) g_bsum[b] = s[0];
}

__global__ void __launch_bounds__(128) k_scan_top() {
    __shared__ int s[128];
    int t = threadIdx.x;
    int v = (t < NBLK) ? g_bsum[t] : 0;
    s[t] = v;
    __syncthreads();
#pragma unroll
    for (int d = 1; d < 128; d <<= 1) {
        int u = (t >= d) ? s[t - d] : 0;
        __syncthreads();
        s[t] += u;
        __syncthreads();
    }
    if (t < NBLK) g_boff[t] = s[t] - v;
    if (t == NBLK - 1) g_off[NN] = s[t];
}

__global__ void __launch_bounds__(1024) k_scan_apply() {
    __shared__ int s[1024];
    int t = threadIdx.x, b = blockIdx.x;
    int i = b * SCAN_B + t;
    int v = (i < NN) ? g_cnt[i] : 0;
    s[t] = v;
    __syncthreads();
#pragma unroll
    for (int d = 1; d < 1024; d <<= 1) {
        int u = (t >= d) ? s[t - d] : 0;
        __syncthreads();
        s[t] += u;
        __syncthreads();
    }
    if (i < NN) {
        int off = g_boff[b] + s[t] - v;
        g_off[i] = off;
        g_cur[i] = off;
    }
}

__global__ void k_fill(const int* __restrict__ ei) {
    int e = blockIdx.x * blockDim.x + threadIdx.x;
    if (e < NE) {
        int c = ei[NE + e];
        int r = ei[e];
        if ((unsigned)c >= (unsigned)NN || (unsigned)r >= (unsigned)NN) return;
        int p = atomicAdd(&g_cur[c], 1);
        g_src[p] = r;
        g_pos[e] = p;
    }
}

// ---------------- mma.m16n8k16 f32 += f16 x f16 ----------------
__device__ __forceinline__ void mma16816(float c[4], const uint32_t a[4],
                                         uint32_t b0, uint32_t b1) {
    asm volatile(
        "mma.sync.aligned.m16n8k16.row.col.f32.f16.f16.f32 "
        "{%0,%1,%2,%3}, {%4,%5,%6,%7}, {%8,%9}, {%0,%1,%2,%3};"
        : "+f"(c[0]), "+f"(c[1]), "+f"(c[2]), "+f"(c[3])
        : "r"(a[0]), "r"(a[1]), "r"(a[2]), "r"(a[3]), "r"(b0), "r"(b1));
}

// ---------------- edge MLP, BOTH stages on tensor cores ----------------
__global__ void __launch_bounds__(256) k_ew(const float* __restrict__ ea,
                                            const float* __restrict__ W1,
                                            const float* __restrict__ W2) {
    __shared__ char  buf[256 * 72 * 2];          // eas / h1s / result rows (aliased)
    __shared__ __half w1h[64][8];
    __shared__ __half w2s[64][72];
    __shared__ int    poss[256];
    __half (*eas)[24] = (__half(*)[24])buf;
    __half (*h1s)[72] = (__half(*)[72])buf;

    int t = threadIdx.x;
    for (int i = t; i < 512; i += 256) w1h[i >> 3][i & 7] = __float2half(W1[i]);
    for (int i = t; i < 4096; i += 256) w2s[i >> 6][i & 63] = __float2half(W2[i]);

    int base = blockIdx.x * 256;
    int w = t >> 5, l = t & 31;
    poss[t] = g_pos[base + t];

    {
        float4 a0 = *(const float4*)&ea[(size_t)(base + t) * 8];
        float4 a1 = *(const float4*)&ea[(size_t)(base + t) * 8 + 4];
        __half2* er = (__half2*)&eas[t][0];
        er[0] = __floats2half2_rn(a0.x, a0.y);
        er[1] = __floats2half2_rn(a0.z, a0.w);
        er[2] = __floats2half2_rn(a1.x, a1.y);
        er[3] = __floats2half2_rn(a1.z, a1.w);
        __half2 z = __floats2half2_rn(0.f, 0.f);
        er[4] = z; er[5] = z; er[6] = z; er[7] = z;
    }
    __syncthreads();

    float c[2][8][4];
#pragma unroll
    for (int mt = 0; mt < 2; mt++)
#pragma unroll
        for (int nt = 0; nt < 8; nt++)
#pragma unroll
            for (int r = 0; r < 4; r++) c[mt][nt][r] = 0.f;

    {   // stage 1 MMA: K=16, upper K-half is zero (B operand literal 0)
        int k0 = (l & 3) * 2;
        uint32_t a[2][4];
#pragma unroll
        for (int mt = 0; mt < 2; mt++) {
            int r = w * 32 + mt * 16 + (l >> 2);
            a[mt][0] = *(const uint32_t*)&eas[r][k0];
            a[mt][1] = *(const uint32_t*)&eas[r + 8][k0];
            a[mt][2] = *(const uint32_t*)&eas[r][k0 + 8];
            a[mt][3] = *(const uint32_t*)&eas[r + 8][k0 + 8];
        }
#pragma unroll
        for (int nt = 0; nt < 8; nt++) {
            int nr = nt * 8 + (l >> 2);
            uint32_t b0 = *(const uint32_t*)&w1h[nr][k0];
            mma16816(c[0][nt], a[0], b0, 0u);
            mma16816(c[1][nt], a[1], b0, 0u);
        }
    }
    __syncthreads();

#pragma unroll
    for (int mt = 0; mt < 2; mt++) {
        int m = w * 32 + mt * 16 + (l >> 2);
#pragma unroll
        for (int nt = 0; nt < 8; nt++) {
            int n = nt * 8 + (l & 3) * 2;
            float v0 = c[mt][nt][0], v1 = c[mt][nt][1];
            float v2 = c[mt][nt][2], v3 = c[mt][nt][3];
            v0 = v0 > 0.f ? v0 : 0.f; v1 = v1 > 0.f ? v1 : 0.f;
            v2 = v2 > 0.f ? v2 : 0.f; v3 = v3 > 0.f ? v3 : 0.f;
            *(__half2*)&h1s[m][n]     = __floats2half2_rn(v0, v1);
            *(__half2*)&h1s[m + 8][n] = __floats2half2_rn(v2, v3);
            c[mt][nt][0] = 0.f; c[mt][nt][1] = 0.f;
            c[mt][nt][2] = 0.f; c[mt][nt][3] = 0.f;
        }
    }
    __syncthreads();

#pragma unroll
    for (int kc = 0; kc < 4; kc++) {   // stage 2 MMA (K=64)
        int k0 = kc * 16 + (l & 3) * 2;
        uint32_t a[2][4];
#pragma unroll
        for (int mt = 0; mt < 2; mt++) {
            int r = w * 32 + mt * 16 + (l >> 2);
            a[mt][0] = *(const uint32_t*)&h1s[r][k0];
            a[mt][1] = *(const uint32_t*)&h1s[r + 8][k0];
            a[mt][2] = *(const uint32_t*)&h1s[r][k0 + 8];
            a[mt][3] = *(const uint32_t*)&h1s[r + 8][k0 + 8];
        }
#pragma unroll
        for (int nt = 0; nt < 8; nt++) {
            int nr = nt * 8 + (l >> 2);
            uint32_t b0 = *(const uint32_t*)&w2s[nr][k0];
            uint32_t b1 = *(const uint32_t*)&w2s[nr][k0 + 8];
            mma16816(c[0][nt], a[0], b0, b1);
            mma16816(c[1][nt], a[1], b0, b1);
        }
    }
    __syncthreads();   // all h1s MMA reads done before result rows overwrite buf

    // stage results into smem rows (relu + fp16)
#pragma unroll
    for (int mt = 0; mt < 2; mt++) {
        int m = w * 32 + mt * 16 + (l >> 2);
#pragma unroll
        for (int nt = 0; nt < 8; nt++) {
            int n = nt * 8 + (l & 3) * 2;
            float v0 = c[mt][nt][0], v1 = c[mt][nt][1];
            float v2 = c[mt][nt][2], v3 = c[mt][nt][3];
            v0 = v0 > 0.f ? v0 : 0.f; v1 = v1 > 0.f ? v1 : 0.f;
            v2 = v2 > 0.f ? v2 : 0.f; v3 = v3 > 0.f ? v3 : 0.f;
            *(__half2*)&h1s[m][n]     = __floats2half2_rn(v0, v1);
            *(__half2*)&h1s[m + 8][n] = __floats2half2_rn(v2, v3);
        }
    }
    __syncthreads();

    // coalesced scatter: 8 lanes x 16B per 128B row, streaming stores
#pragma unroll
    for (int i = 0; i < 8; i++) {
        int row = (t >> 3) + i * 32;
        int col = t & 7;
        uint4 v = *(const uint4*)&h1s[row][col * 8];
        __stcs((uint4*)&g_ew[(size_t)poss[row] * 64 + col * 8], v);
    }
}

// ---------------- degree / dinv (warp per node, half2, unroll 2, ldcs) ----------------
__global__ void __launch_bounds__(256) k_deg() {
    int w = (blockIdx.x * blockDim.x + threadIdx.x) >> 5;
    int lane = threadIdx.x & 31;
    if (w >= NN) return;
    int s = g_off[w], e = g_off[w + 1];
    const __half2* ewv = (const __half2*)g_ew;
    float2 d0 = make_float2(1.f, 1.f);
    float2 d1 = make_float2(0.f, 0.f);
    int p = s;
    for (; p + 2 <= e; p += 2) {
        float2 v0 = __half22float2(__ldcs(&ewv[(size_t)p * 32 + lane]));
        float2 v1 = __half22float2(__ldcs(&ewv[(size_t)(p + 1) * 32 + lane]));
        d0.x += v0.x; d0.y += v0.y;
        d1.x += v1.x; d1.y += v1.y;
    }
    if (p < e) {
        float2 v0 = __half22float2(__ldcs(&ewv[(size_t)p * 32 + lane]));
        d0.x += v0.x; d0.y += v0.y;
    }
    float2 r; r.x = rsqrtf(d0.x + d1.x); r.y = rsqrtf(d0.y + d1.y);
    ((float2*)g_dinv)[(size_t)w * 32 + lane] = r;
}

// ---------------- aggregation (warp per node), unroll 4, int4 src, fp16 y, ldcs ew ----------------
__global__ void __launch_bounds__(256) k_agg(const float* __restrict__ bc) {
    int w = (blockIdx.x * blockDim.x + threadIdx.x) >> 5;
    int lane = threadIdx.x & 31;
    if (w >= NN) return;
    int s = g_off[w], e = g_off[w + 1];
    const __half2* yv  = (const __half2*)g_y;
    const __half2* ewv = (const __half2*)g_ew;
    float2 a0 = __half22float2(yv[(size_t)w * 32 + lane]);   // self loop
    float2 a1 = make_float2(0.f, 0.f);
    float2 a2 = make_float2(0.f, 0.f);
    float2 a3 = make_float2(0.f, 0.f);
    int p = s;
    for (; p < e && (p & 3); p++) {
        int s0 = g_src[p];
        float2 f0 = __half22float2(__ldcs(&ewv[(size_t)p * 32 + lane]));
        float2 y0 = __half22float2(yv[(size_t)s0 * 32 + lane]);
        a0.x = fmaf(f0.x, y0.x, a0.x); a0.y = fmaf(f0.y, y0.y, a0.y);
    }
    for (; p + 4 <= e; p += 4) {
        int4 sv = *(const int4*)&g_src[p];
        __half2 h0 = __ldcs(&ewv[(size_t)p * 32 + lane]);
        __half2 h1 = __ldcs(&ewv[(size_t)(p + 1) * 32 + lane]);
        __half2 h2 = __ldcs(&ewv[(size_t)(p + 2) * 32 + lane]);
        __half2 h3 = __ldcs(&ewv[(size_t)(p + 3) * 32 + lane]);
        float2 y0 = __half22float2(yv[(size_t)sv.x * 32 + lane]);
        float2 y1 = __half22float2(yv[(size_t)sv.y * 32 + lane]);
        float2 y2 = __half22float2(yv[(size_t)sv.z * 32 + lane]);
        float2 y3 = __half22float2(yv[(size_t)sv.w * 32 + lane]);
        float2 f0 = __half22float2(h0), f1 = __half22float2(h1);
        float2 f2 = __half22float2(h2), f3 = __half22float2(h3);
        a0.x = fmaf(f0.x, y0.x, a0.x); a0.y = fmaf(f0.y, y0.y, a0.y);
        a1.x = fmaf(f1.x, y1.x, a1.x); a1.y = fmaf(f1.y, y1.y, a1.y);
        a2.x = fmaf(f2.x, y2.x, a2.x); a2.y = fmaf(f2.y, y2.y, a2.y);
        a3.x = fmaf(f3.x, y3.x, a3.x); a3.y = fmaf(f3.y, y3.y, a3.y);
    }
    for (; p < e; p++) {
        int s0 = g_src[p];
        float2 f0 = __half22float2(__ldcs(&ewv[(size_t)p * 32 + lane]));
        float2 y0 = __half22float2(yv[(size_t)s0 * 32 + lane]);
        a0.x = fmaf(f0.x, y0.x, a0.x); a0.y = fmaf(f0.y, y0.y, a0.y);
    }
    float2 dv = ((const float2*)g_dinv)[(size_t)w * 32 + lane];
    float rx = fmaf(dv.x, (a0.x + a1.x) + (a2.x + a3.x), bc[2 * lane]);
    float ry = fmaf(dv.y, (a0.y + a1.y) + (a2.y + a3.y), bc[2 * lane + 1]);
    ((__half2*)g_hagg)[(size_t)w * 32 + lane] = __floats2half2_rn(rx, ry);
}

// ---------------- tensor-core GEMM: C[N,64] = A[N,128] @ W[64,128]^T ----------------
// mode 0: A = xin fp32 (lda 128), bias=bi -> stores g_xlin (fp16) + y
// mode 1: pass0 A = g_xlin fp16 (raw), pass1 A = g_hagg fp16 (raw); resid = g_xlin.
//         Stores ONLY y (l<2, ywc) or out (l=2, Wo) -- the h tensor is dead.
__global__ void __launch_bounds__(256) k_gemm(const float* __restrict__ xin,
                                              const float* __restrict__ W,
                                              const float* __restrict__ bias,
                                              int mode,
                                              const float* __restrict__ ywc,
                                              const float* __restrict__ Wo,
                                              float* __restrict__ out) {
    __shared__ __half As[128][72];
    __shared__ __half Bs[64][136];
    int t = threadIdx.x;
    {   // vectorized W -> Bs (fp16)
        const float4* W4 = (const float4*)W;
        for (int i = t; i < 2048; i += 256) {
            float4 v = W4[i];
            int r = i >> 5, c4 = (i & 31) * 4;
            Bs[r][c4]     = __float2half(v.x);
            Bs[r][c4 + 1] = __float2half(v.y);
            Bs[r][c4 + 2] = __float2half(v.z);
            Bs[r][c4 + 3] = __float2half(v.w);
        }
    }

    int bm = blockIdx.x * 128;
    int w = t >> 5, l = t & 31;
    float c[8][4];
#pragma unroll
    for (int nt = 0; nt < 8; nt++)
#pragma unroll
        for (int r = 0; r < 4; r++) c[nt][r] = 0.f;

    int lrow = t >> 1, lc0 = (t & 1) * 32;
    bool lvalid = (bm + lrow) < NN;

#pragma unroll
    for (int pass = 0; pass < 2; pass++) {
        __syncthreads();
        if (mode == 1) {
            // both operands already fp16: raw 16B copies
            const __half* srcp = (pass ? g_hagg : g_xlin) + (size_t)(bm + lrow) * 64 + lc0;
#pragma unroll
            for (int ch = 0; ch < 4; ch++) {
                uint4 pk = make_uint4(0u, 0u, 0u, 0u);
                if (lvalid) pk = *(const uint4*)&srcp[ch * 8];
                *(uint4*)&As[lrow][lc0 + ch * 8] = pk;
            }
        } else {
            const float* srcp = &xin[(size_t)(bm + lrow) * 128 + pass * 64 + lc0];
#pragma unroll
            for (int ch = 0; ch < 4; ch++) {
                float4 v0 = make_float4(0.f, 0.f, 0.f, 0.f), v1 = v0;
                if (lvalid) {
                    v0 = *(const float4*)&srcp[ch * 8];
                    v1 = *(const float4*)&srcp[ch * 8 + 4];
                }
                __half2 h0 = __floats2half2_rn(v0.x, v0.y);
                __half2 h1 = __floats2half2_rn(v0.z, v0.w);
                __half2 h2 = __floats2half2_rn(v1.x, v1.y);
                __half2 h3 = __floats2half2_rn(v1.z, v1.w);
                uint4 pk;
                pk.x = *(uint32_t*)&h0; pk.y = *(uint32_t*)&h1;
                pk.z = *(uint32_t*)&h2; pk.w = *(uint32_t*)&h3;
                *(uint4*)&As[lrow][lc0 + ch * 8] = pk;
            }
        }
        __syncthreads();
#pragma unroll
        for (int kc = 0; kc < 4; kc++) {
            int k0 = kc * 16 + (l & 3) * 2;
            int row = w * 16 + (l >> 2);
            uint32_t a[4];
            a[0] = *(const uint32_t*)&As[row][k0];
            a[1] = *(const uint32_t*)&As[row + 8][k0];
            a[2] = *(const uint32_t*)&As[row][k0 + 8];
            a[3] = *(const uint32_t*)&As[row + 8][k0 + 8];
            int kb = pass * 64 + k0;
#pragma unroll
            for (int nt = 0; nt < 8; nt++) {
                int nr = nt * 8 + (l >> 2);
                uint32_t b0 = *(const uint32_t*)&Bs[nr][kb];
                uint32_t b1 = *(const uint32_t*)&Bs[nr][kb + 8];
                mma16816(c[nt], a, b0, b1);
            }
        }
    }

    int m0 = bm + w * 16 + (l >> 2);
    int n0 = (l & 3) * 2;

    if (Wo) {   // fused final output (l=2)
        const __half2* xr = (const __half2*)g_xlin;
        float oacc[2] = {0.f, 0.f};
#pragma unroll
        for (int nt = 0; nt < 8; nt++) {
            int n = nt * 8 + n0;
            float wx0 = Wo[n], wx1 = Wo[n + 1];
            float wh0 = Wo[64 + n], wh1 = Wo[64 + n + 1];
#pragma unroll
            for (int rr = 0; rr < 2; rr++) {
                int m = m0 + rr * 8;
                if (m >= NN) continue;
                float2 rv = __half22float2(xr[((size_t)m * 64 + n) >> 1]);
                float h0 = c[nt][rr * 2] + rv.x;
                float h1 = c[nt][rr * 2 + 1] + rv.y;
                h0 = h0 > 0.f ? h0 : 0.f;
                h1 = h1 > 0.f ? h1 : 0.f;
                oacc[rr] += rv.x * wx0 + rv.y * wx1 + h0 * wh0 + h1 * wh1;
            }
        }
#pragma unroll
        for (int rr = 0; rr < 2; rr++) {
            oacc[rr] += __shfl_xor_sync(0xffffffffu, oacc[rr], 1);
            oacc[rr] += __shfl_xor_sync(0xffffffffu, oacc[rr], 2);
        }
        if ((l & 3) == 0) {
            if (m0 < NN)     out[m0]     = oacc[0];
            if (m0 + 8 < NN) out[m0 + 8] = oacc[1];
        }
        return;
    }

#pragma unroll
    for (int nt = 0; nt < 8; nt++) {
        int n = nt * 8 + n0;
#pragma unroll
        for (int rr = 0; rr < 2; rr++) {
            int m = m0 + rr * 8;
            if (m >= NN) continue;
            float v0 = c[nt][rr * 2], v1 = c[nt][rr * 2 + 1];
            if (mode == 0) {
                v0 += bias[n]; v1 += bias[n + 1];
                *(__half2*)&g_xlin[(size_t)m * 64 + n] = __floats2half2_rn(v0, v1);
            } else {
                float2 rv = __half22float2(*(const __half2*)&g_xlin[(size_t)m * 64 + n]);
                v0 += rv.x; v1 += rv.y;
            }
            if (ywc) {
                float2 dv = *(const float2*)&g_dinv[(size_t)m * 64 + n];
                float r0 = v0 > 0.f ? v0 : 0.f;
                float r1 = v1 > 0.f ? v1 : 0.f;
                *(__half2*)&g_y[(size_t)m * 64 + n] =
                    __floats2half2_rn(dv.x * r0 * ywc[n], dv.y * r1 * ywc[n + 1]);
            }
        }
    }
}

// ---------------- host ----------------
extern "C" void kernel_launch(void* const* d_in, const int* in_sizes, int n_in,
                              void* d_out, int out_size) {
    const float* x  = (const float*)d_in[0];
    const int*   ei = (const int*)d_in[1];     // int32 [2, E]
    const float* ea = (const float*)d_in[2];
    const float* W1 = (const float*)d_in[3];
    const float* W2 = (const float*)d_in[4];
    const float* Wi = (const float*)d_in[5];
    const float* bi = (const float*)d_in[6];
    const float* wc = (const float*)d_in[7];
    const float* bc = (const float*)d_in[8];
    const float* Wl = (const float*)d_in[9];
    const float* Wo = (const float*)d_in[10];
    float* out = (float*)d_out;

    const int WPB = 8;
    k_zero<<<(NN + 1023) / 1024, 1024>>>();
    k_count<<<(NE + 255) / 256, 256>>>(ei);
    k_scan_sum<<<NBLK, 1024>>>();
    k_scan_top<<<1, 128>>>();
    k_scan_apply<<<NBLK, 1024>>>();
    k_fill<<<(NE + 255) / 256, 256>>>(ei);
    k_ew<<<NE / 256, 256>>>(ea, W1, W2);
    k_deg<<<(NN + WPB - 1) / WPB, 256>>>();
    k_gemm<<<(NN + 127) / 128, 256>>>(x, Wi, bi, 0, wc, nullptr, nullptr);
    for (int l = 0; l < 3; l++) {
        k_agg<<<(NN + WPB - 1) / WPB, 256>>>(bc + l * 64);
        k_gemm<<<(NN + 127) / 128, 256>>>(x, Wl + l * 64 * 128, nullptr, 1,
                                          l < 2 ? wc + (l + 1) * 64 : nullptr,
                                          l == 2 ? Wo : nullptr,
                                          l == 2 ? out : nullptr);
    }
}